// round 9
// baseline (speedup 1.0000x reference)
#include <cuda_runtime.h>
#include <cuda_bf16.h>
#include <cstdint>

// ---------------------------------------------------------------------------
// Problem constants
#define NRED   100000
#define TT     32
#define KFEAT  512
#define THRESH 10.0f
#define KWTA   16

// GEMM tiling: 148 k-splits x 2 m-tiles = 296 CTAs (2 CTAs/SM)
#define SPLITS 148
#define KTILE  32
#define NT     22
#define CHUNK  (KTILE * NT)        // 704
#define KPAD   (SPLITS * CHUNK)    // 104192
#define MTILE  256

// smem: A: 2 stages x 32KB. Row m (0..255) is 128B: hi k0-31 at bytes 0-63,
//       lo at 64-127, SW128-swizzled. B: 2 stages x 4KB, t-pairs per 128B row.
#define SM_A    0
#define SM_ASTG 32768
#define SM_B    (2 * SM_ASTG)      // 65536
#define SM_BSTG 4096
#define SMEMB   (SM_B + 2 * SM_BSTG)   // 73728

// Device scratch (static — no dynamic allocation allowed)
__device__ __align__(128) __nv_bfloat16 g_B[(size_t)64 * KPAD];  // 13.3MB
__device__ float g_partial[SPLITS * TT * KFEAT];   // 9.7MB
__device__ float g_dot[TT * KFEAT];
__device__ float g_tot[KFEAT];
__device__ int   g_cntp[8 * KFEAT];

// ---------------------------------------------------------------------------
__device__ __forceinline__ uint32_t smem_u32(const void* p) {
    uint32_t a;
    asm("{ .reg .u64 t; cvta.to.shared.u64 t, %1; cvt.u32.u64 %0, t; }"
        : "=r"(a) : "l"(p));
    return a;
}
__device__ __forceinline__ uint32_t sw128(uint32_t off) {
    return off ^ ((off >> 3) & 0x70);
}
__device__ __forceinline__ uint32_t packbf(__nv_bfloat16 a, __nv_bfloat16 b) {
    __nv_bfloat162 v; v.x = a; v.y = b;
    return *reinterpret_cast<uint32_t*>(&v);
}
__device__ __forceinline__ void split2(float x, __nv_bfloat16& h, __nv_bfloat16& l) {
    h = __float2bfloat16(x);
    l = __float2bfloat16(x - __bfloat162float(h));
}
__device__ __forceinline__ void cpasync16(uint32_t dst, const void* src) {
    asm volatile("cp.async.cg.shared.global [%0], [%1], 16;"
                 :: "r"(dst), "l"(src) : "memory");
}
__device__ __forceinline__ void cpasync_commit() {
    asm volatile("cp.async.commit_group;" ::: "memory");
}
__device__ __forceinline__ void cpasync_wait0() {
    asm volatile("cp.async.wait_group 0;" ::: "memory");
}
#define LDSM4(R, ADDR)                                                        \
    asm volatile("ldmatrix.sync.aligned.m8n8.x4.shared.b16 {%0,%1,%2,%3}, [%4];" \
                 : "=r"((R)[0]), "=r"((R)[1]), "=r"((R)[2]), "=r"((R)[3])     \
                 : "r"(ADDR))
#define MMA16816(D, A, B0, B1)                                                \
    asm volatile("mma.sync.aligned.m16n8k16.row.col.f32.bf16.bf16.f32 "       \
                 "{%0,%1,%2,%3}, {%4,%5,%6,%7}, {%8,%9}, {%0,%1,%2,%3};"      \
                 : "+f"((D)[0]), "+f"((D)[1]), "+f"((D)[2]), "+f"((D)[3])     \
                 : "r"((A)[0]), "r"((A)[1]), "r"((A)[2]), "r"((A)[3]),        \
                   "r"(B0), "r"(B1))

// ---------------------------------------------------------------------------
// Split rec_field into bf16 hi/lo, zero-padded to KPAD
// ---------------------------------------------------------------------------
__global__ void __launch_bounds__(256)
conv_kernel(const float* __restrict__ R) {
    const int k4 = (blockIdx.x * 256 + threadIdx.x) * 4;
    if (k4 >= KPAD) return;
    const bool ok = (k4 < NRED);
#pragma unroll 4
    for (int t = 0; t < TT; t++) {
        float4 x = ok ? *(const float4*)(R + (size_t)t * NRED + k4)
                      : make_float4(0.f, 0.f, 0.f, 0.f);
        __nv_bfloat16 h0,h1,h2,h3,l0,l1,l2,l3;
        split2(x.x, h0, l0); split2(x.y, h1, l1);
        split2(x.z, h2, l2); split2(x.w, h3, l3);
        *(uint2*)(g_B + (size_t)t * KPAD + k4)        = make_uint2(packbf(h0,h1), packbf(h2,h3));
        *(uint2*)(g_B + (size_t)(t + 32) * KPAD + k4) = make_uint2(packbf(l0,l1), packbf(l2,l3));
    }
}

// ---------------------------------------------------------------------------
// GEMM: bf16 3-term split (hi*hi + lo*hi + hi*lo, all into one accumulator).
// grid (148, 2), 256 threads, 2 CTAs/SM. Each warp: 32 m-rows x 32 t-cols.
// ---------------------------------------------------------------------------
__global__ void __launch_bounds__(256, 2)
gemm_kernel(const float* __restrict__ W) {
    extern __shared__ char smem[];
    const uint32_t sb = smem_u32(smem);

    const int tid  = threadIdx.x;
    const int lane = tid & 31;
    const int wrp  = tid >> 5;
    const int split = blockIdx.x;
    const int m0    = blockIdx.y * MTILE;
    const int kbase = split * CHUNK;

    // W loader: warp = 4 rows x 8 k-quads per LDG; 8 iters -> 32 rows
    const int row_off = lane >> 3;             // 0..3
    const int kq      = lane & 7;              // 0..7
    // B cp.async loader: thread -> (t = tid>>2, 16B chunk c = tid&3)
    const int bt = tid >> 2;
    const int bc = tid & 3;
    const uint32_t bdst_off = (uint32_t)(bt >> 1) * 128 + (uint32_t)(bt & 1) * 64
                            + (uint32_t)bc * 16;

    // A ldmatrix: strips 2*wrp, 2*wrp+1 (A-convention: bit3 -> row+8, bit4 -> k+16)
    const int arow0 = (2 * wrp) * 16 + (lane & 7) + ((lane >> 3) & 1) * 8;
    const int arow1 = arow0 + 16;
    const uint32_t a_kb0 = ((lane >> 4) & 1) * 16;
    const uint32_t a_off0 = (uint32_t)arow0 * 128, a_xr0 = (uint32_t)(arow0 & 7) << 4;
    const uint32_t a_off1 = (uint32_t)arow1 * 128, a_xr1 = (uint32_t)(arow1 & 7) << 4;
    // B ldmatrix (B-convention: bit4 -> t+8, bit3 -> k+16); t-pair packed rows
    const int tbase = (lane & 7) + ((lane >> 4) & 1) * 8;       // 0..15
    const uint32_t b_row = (uint32_t)(tbase >> 1) * 128;        // row within t-block
    const uint32_t b_par = (uint32_t)(tbase & 1) * 64;
    const uint32_t b_xr  = (uint32_t)((tbase >> 1) & 7) << 4;
    const uint32_t b_kb0 = ((lane >> 3) & 1) * 16;

    float d[2][4][4];
#pragma unroll
    for (int s = 0; s < 2; s++)
#pragma unroll
        for (int i = 0; i < 4; i++)
#pragma unroll
            for (int j = 0; j < 4; j++) d[s][i][j] = 0.0f;

    float4 wr[8];
    const float4 z4 = make_float4(0.f, 0.f, 0.f, 0.f);

#define LOAD_W(TL) do {                                                      \
    const int kp_ = kbase + (TL) * KTILE + kq * 4;                           \
    const bool ok_ = (kp_ < NRED);                                           \
    const float* wp_ = W + (size_t)(m0 + wrp * 4 + row_off) * NRED + kp_;    \
    _Pragma("unroll")                                                        \
    for (int i = 0; i < 8; i++)                                              \
        wr[i] = ok_ ? *(const float4*)(wp_ + (size_t)32 * i * NRED) : z4;    \
} while (0)

#define ASYNC_B(TL, BUF) do {                                                \
    const __nv_bfloat16* src_ = g_B + (size_t)bt * KPAD                      \
                              + (kbase + (TL) * KTILE) + bc * 8;             \
    cpasync16(sb + SM_B + (BUF) * SM_BSTG + sw128(bdst_off), src_);          \
    cpasync_commit();                                                        \
} while (0)

#define STS_A(BUF) do {                                                      \
    char* ab_ = smem + SM_A + (BUF) * SM_ASTG;                               \
    _Pragma("unroll")                                                        \
    for (int i = 0; i < 8; i++) {                                            \
        const int row_ = i * 32 + wrp * 4 + row_off;                         \
        const uint32_t base_ = (uint32_t)row_ * 128;                         \
        float4 f_ = wr[i];                                                   \
        __nv_bfloat16 h0,h1,h2,h3,l0,l1,l2,l3;                               \
        split2(f_.x, h0, l0); split2(f_.y, h1, l1);                          \
        split2(f_.z, h2, l2); split2(f_.w, h3, l3);                          \
        *(uint2*)(ab_ + sw128(base_ + kq * 8))      = make_uint2(packbf(h0,h1), packbf(h2,h3)); \
        *(uint2*)(ab_ + sw128(base_ + 64 + kq * 8)) = make_uint2(packbf(l0,l1), packbf(l2,l3)); \
    }                                                                        \
} while (0)

#define COMPUTE(BUF) do {                                                    \
    const uint32_t sa_ = sb + SM_A + (BUF) * SM_ASTG;                        \
    const uint32_t sB_ = sb + SM_B + (BUF) * SM_BSTG;                        \
    _Pragma("unroll")                                                        \
    for (int ks = 0; ks < 2; ks++) {                                         \
        uint32_t ah0[4], ah1[4], al0[4], al1[4];                             \
        uint32_t bh0[4], bh1[4], bl0[4], bl1[4];                             \
        const uint32_t ch_ = (uint32_t)(ks * 32) + a_kb0;                    \
        LDSM4(ah0, sa_ + a_off0 + (ch_ ^ a_xr0));                            \
        LDSM4(ah1, sa_ + a_off1 + (ch_ ^ a_xr1));                            \
        LDSM4(al0, sa_ + a_off0 + ((ch_ + 64) ^ a_xr0));                     \
        LDSM4(al1, sa_ + a_off1 + ((ch_ + 64) ^ a_xr1));                     \
        const uint32_t cb_ = (b_par + (uint32_t)(ks * 32) + b_kb0) ^ b_xr;   \
        LDSM4(bh0, sB_ + 0 * 1024 + b_row + cb_);                            \
        LDSM4(bh1, sB_ + 1 * 1024 + b_row + cb_);                            \
        LDSM4(bl0, sB_ + 2 * 1024 + b_row + cb_);                            \
        LDSM4(bl1, sB_ + 3 * 1024 + b_row + cb_);                            \
        MMA16816(d[0][0], ah0, bh0[0], bh0[1]);                              \
        MMA16816(d[0][1], ah0, bh0[2], bh0[3]);                              \
        MMA16816(d[0][2], ah0, bh1[0], bh1[1]);                              \
        MMA16816(d[0][3], ah0, bh1[2], bh1[3]);                              \
        MMA16816(d[1][0], ah1, bh0[0], bh0[1]);                              \
        MMA16816(d[1][1], ah1, bh0[2], bh0[3]);                              \
        MMA16816(d[1][2], ah1, bh1[0], bh1[1]);                              \
        MMA16816(d[1][3], ah1, bh1[2], bh1[3]);                              \
        MMA16816(d[0][0], al0, bh0[0], bh0[1]);                              \
        MMA16816(d[0][1], al0, bh0[2], bh0[3]);                              \
        MMA16816(d[0][2], al0, bh1[0], bh1[1]);                              \
        MMA16816(d[0][3], al0, bh1[2], bh1[3]);                              \
        MMA16816(d[1][0], al1, bh0[0], bh0[1]);                              \
        MMA16816(d[1][1], al1, bh0[2], bh0[3]);                              \
        MMA16816(d[1][2], al1, bh1[0], bh1[1]);                              \
        MMA16816(d[1][3], al1, bh1[2], bh1[3]);                              \
        MMA16816(d[0][0], ah0, bl0[0], bl0[1]);                              \
        MMA16816(d[0][1], ah0, bl0[2], bl0[3]);                              \
        MMA16816(d[0][2], ah0, bl1[0], bl1[1]);                              \
        MMA16816(d[0][3], ah0, bl1[2], bl1[3]);                              \
        MMA16816(d[1][0], ah1, bl0[0], bl0[1]);                              \
        MMA16816(d[1][1], ah1, bl0[2], bl0[3]);                              \
        MMA16816(d[1][2], ah1, bl1[0], bl1[1]);                              \
        MMA16816(d[1][3], ah1, bl1[2], bl1[3]);                              \
    }                                                                        \
} while (0)

    ASYNC_B(0, 0);
    LOAD_W(0);
    STS_A(0);
    cpasync_wait0();
    __syncthreads();

    for (int tl = 0; tl < NT; tl++) {
        if (tl + 1 < NT) {
            ASYNC_B(tl + 1, (tl + 1) & 1);
            LOAD_W(tl + 1);
        }
        COMPUTE(tl & 1);
        if (tl + 1 < NT) {
            STS_A((tl + 1) & 1);
            cpasync_wait0();
            __syncthreads();
        }
    }

    // ---- epilogue: direct writes, no fold ----
    float* gp = g_partial + (size_t)split * (TT * KFEAT) + m0;
    const int rbase = lane >> 2;
    const int c0 = (lane & 3) * 2;
#pragma unroll
    for (int s = 0; s < 2; s++) {
        const int feat = wrp * 32 + s * 16 + rbase;
#pragma unroll
        for (int n = 0; n < 4; n++) {
            const int t0 = n * 8 + c0;
            gp[(size_t)t0 * KFEAT + feat]           = d[s][n][0];
            gp[(size_t)(t0 + 1) * KFEAT + feat]     = d[s][n][1];
            gp[(size_t)t0 * KFEAT + feat + 8]       = d[s][n][2];
            gp[(size_t)(t0 + 1) * KFEAT + feat + 8] = d[s][n][3];
        }
    }
}

// ---------------------------------------------------------------------------
// Reduce partials across splits: g_dot[t][feat]
// ---------------------------------------------------------------------------
__global__ void __launch_bounds__(256)
reduce_kernel() {
    const int j = blockIdx.x * 256 + threadIdx.x;
    float s = 0.0f;
#pragma unroll 4
    for (int sp = 0; sp < SPLITS; sp++) s += g_partial[sp * (TT * KFEAT) + j];
    g_dot[j] = s;
}

// ---------------------------------------------------------------------------
// Count kernel: 8 blocks x 512. Each block redundantly computes the exact
// reference totals (deterministic, identical across blocks), then counts
// ranks for its 64-feature segment. Block also writes g_tot (same values).
// ---------------------------------------------------------------------------
__global__ void __launch_bounds__(512, 1)
count_kernel() {
    __shared__ float tot_s[KFEAT];
    __shared__ float red_s[16];
    __shared__ float v_s;
    const int k = threadIdx.x;
    const int b = blockIdx.x;

    int nspk = 0;
#pragma unroll
    for (int t = 0; t < TT; t++) {
        float dd = g_dot[t * KFEAT + k];
        nspk += (dd > THRESH) ? 1 : 0;
    }
    int first = TT - nspk;
    if (first > TT - 1) first = TT - 1;
    if (first < 0) first = 0;
    float dv = g_dot[first * KFEAT + k];
    float value = (dv > THRESH) ? dv : 0.0f;
    float sval = (nspk > 0) ? value : 0.0f;

    float m = sval;
#pragma unroll
    for (int o = 16; o > 0; o >>= 1)
        m = fmaxf(m, __shfl_xor_sync(0xffffffffu, m, o));
    if ((k & 31) == 0) red_s[k >> 5] = m;
    __syncthreads();
    if (k == 0) {
        float mm = red_s[0];
#pragma unroll
        for (int i = 1; i < 16; i++) mm = fmaxf(mm, red_s[i]);
        v_s = mm * (float)TT;
    }
    __syncthreads();

    const float fns = (float)nspk;
    const float total = fns * value + fns * v_s;
    tot_s[k] = total;
    g_tot[k] = total;
    __syncthreads();

    // rank-count against segment [64b, 64b+64)
    const int jbase = b * 64;
    int cnt = 0;
#pragma unroll
    for (int jj = 0; jj < 16; jj++) {
        float4 tv = *(const float4*)(tot_s + jbase + jj * 4);
        const int j0 = jbase + jj * 4;
        cnt += ((tv.x > total) || (tv.x == total && (j0 + 0) < k)) ? 1 : 0;
        cnt += ((tv.y > total) || (tv.y == total && (j0 + 1) < k)) ? 1 : 0;
        cnt += ((tv.z > total) || (tv.z == total && (j0 + 2) < k)) ? 1 : 0;
        cnt += ((tv.w > total) || (tv.w == total && (j0 + 3) < k)) ? 1 : 0;
    }
    g_cntp[b * KFEAT + k] = cnt;
}

// ---------------------------------------------------------------------------
// Output: 1 block x 512
// ---------------------------------------------------------------------------
__global__ void __launch_bounds__(512, 1)
output_kernel(float* __restrict__ out) {
    const int k = threadIdx.x;
    int cnt = 0;
#pragma unroll
    for (int b = 0; b < 8; b++) cnt += g_cntp[b * KFEAT + k];
    const float total = g_tot[k];
    const bool win = (total > 0.0f) && (cnt < KWTA);
#pragma unroll
    for (int t = 0; t < TT; t++) {
        float dd = g_dot[t * KFEAT + k];
        out[t * KFEAT + k] = (win && dd > THRESH) ? 1.0f : 0.0f;
    }
}

// ---------------------------------------------------------------------------
extern "C" void kernel_launch(void* const* d_in, const int* in_sizes, int n_in,
                              void* d_out, int out_size) {
    const float* a = (const float*)d_in[0];
    const float* b = (const float*)d_in[1];
    const float* rec = a;
    const float* wgt = b;
    if (in_sizes[0] > in_sizes[1]) { rec = b; wgt = a; }

    cudaFuncSetAttribute(gemm_kernel,
                         cudaFuncAttributeMaxDynamicSharedMemorySize, SMEMB);

    conv_kernel<<<(KPAD / 4 + 255) / 256, 256>>>(rec);
    dim3 grid(SPLITS, 2);
    gemm_kernel<<<grid, 256, SMEMB>>>(wgt);
    reduce_kernel<<<(TT * KFEAT) / 256, 256>>>();
    count_kernel<<<8, 512>>>();
    output_kernel<<<1, 512>>>((float*)d_out);
}

// round 10
// speedup vs baseline: 1.1161x; 1.1161x over previous
#include <cuda_runtime.h>
#include <cuda_bf16.h>
#include <cstdint>

// ---------------------------------------------------------------------------
// Problem constants
#define NRED   100000
#define TT     32
#define KFEAT  512
#define THRESH 10.0f
#define KWTA   16

// GEMM tiling: 74 k-splits x 4 m-tiles = 296 CTAs (2 CTAs/SM)  [R7 proven]
#define SPLITS 74
#define KTILE  64
#define NT     22
#define CHUNK  (KTILE * NT)        // 1408
#define KPAD   (SPLITS * CHUNK)    // 104192
#define MTILE  128

#define SM_A    0
#define SM_ASTG 32768
#define SM_B    (2 * SM_ASTG)      // 65536
#define SM_BSTG 8192
#define SMEMB   (SM_B + 2 * SM_BSTG)   // 81920

// Device scratch (static — no dynamic allocation allowed)
__device__ __align__(128) __nv_bfloat16 g_B[(size_t)64 * KPAD];  // 13.3MB
__device__ float g_partial[SPLITS * TT * KFEAT];
__device__ float g_dot[TT * KFEAT];                // [t][feat]

// ---------------------------------------------------------------------------
__device__ __forceinline__ uint32_t smem_u32(const void* p) {
    uint32_t a;
    asm("{ .reg .u64 t; cvta.to.shared.u64 t, %1; cvt.u32.u64 %0, t; }"
        : "=r"(a) : "l"(p));
    return a;
}
__device__ __forceinline__ uint32_t sw128(uint32_t off) {
    return off ^ ((off >> 3) & 0x70);
}
__device__ __forceinline__ uint32_t packbf(__nv_bfloat16 a, __nv_bfloat16 b) {
    __nv_bfloat162 v; v.x = a; v.y = b;
    return *reinterpret_cast<uint32_t*>(&v);
}
__device__ __forceinline__ void split2(float x, __nv_bfloat16& h, __nv_bfloat16& l) {
    h = __float2bfloat16(x);
    l = __float2bfloat16(x - __bfloat162float(h));
}
__device__ __forceinline__ void cpasync16(uint32_t dst, const void* src) {
    asm volatile("cp.async.cg.shared.global [%0], [%1], 16;"
                 :: "r"(dst), "l"(src) : "memory");
}
__device__ __forceinline__ void cpasync_commit() {
    asm volatile("cp.async.commit_group;" ::: "memory");
}
__device__ __forceinline__ void cpasync_wait0() {
    asm volatile("cp.async.wait_group 0;" ::: "memory");
}
#define LDSM4(R, ADDR)                                                        \
    asm volatile("ldmatrix.sync.aligned.m8n8.x4.shared.b16 {%0,%1,%2,%3}, [%4];" \
                 : "=r"((R)[0]), "=r"((R)[1]), "=r"((R)[2]), "=r"((R)[3])     \
                 : "r"(ADDR))
#define MMA16816(D, A, B0, B1)                                                \
    asm volatile("mma.sync.aligned.m16n8k16.row.col.f32.bf16.bf16.f32 "       \
                 "{%0,%1,%2,%3}, {%4,%5,%6,%7}, {%8,%9}, {%0,%1,%2,%3};"      \
                 : "+f"((D)[0]), "+f"((D)[1]), "+f"((D)[2]), "+f"((D)[3])     \
                 : "r"((A)[0]), "r"((A)[1]), "r"((A)[2]), "r"((A)[3]),        \
                   "r"(B0), "r"(B1))

// ---------------------------------------------------------------------------
// Split rec_field into bf16 hi/lo, zero-padded to KPAD
// ---------------------------------------------------------------------------
__global__ void __launch_bounds__(256)
conv_kernel(const float* __restrict__ R) {
    const int k4 = (blockIdx.x * 256 + threadIdx.x) * 4;
    if (k4 >= KPAD) return;
    const bool ok = (k4 < NRED);
#pragma unroll 4
    for (int t = 0; t < TT; t++) {
        float4 x = ok ? *(const float4*)(R + (size_t)t * NRED + k4)
                      : make_float4(0.f, 0.f, 0.f, 0.f);
        __nv_bfloat16 h0,h1,h2,h3,l0,l1,l2,l3;
        split2(x.x, h0, l0); split2(x.y, h1, l1);
        split2(x.z, h2, l2); split2(x.w, h3, l3);
        *(uint2*)(g_B + (size_t)t * KPAD + k4)        = make_uint2(packbf(h0,h1), packbf(h2,h3));
        *(uint2*)(g_B + (size_t)(t + 32) * KPAD + k4) = make_uint2(packbf(l0,l1), packbf(l2,l3));
    }
}

// ---------------------------------------------------------------------------
// GEMM: bf16 3-term split — EXACT R7 structure (best measured: ~49us)
// ---------------------------------------------------------------------------
__global__ void __launch_bounds__(256, 2)
gemm_kernel(const float* __restrict__ W) {
    extern __shared__ char smem[];
    const uint32_t sb = smem_u32(smem);

    const int tid  = threadIdx.x;
    const int lane = tid & 31;
    const int wrp  = tid >> 5;
    const int q    = wrp & 3;
    const int grp  = wrp >> 2;
    const int split = blockIdx.x;
    const int m0    = blockIdx.y * MTILE;
    const int kbase = split * CHUNK;

    const int row_off = lane >> 4;
    const int kq      = lane & 15;
    const int brow = tid >> 2;
    const uint32_t bcol = (uint32_t)(tid & 3) * 32;

    const int s0 = 2 * q, s1 = 2 * q + 1;
    const int arow0 = s0 * 16 + (lane & 7) + ((lane >> 3) & 1) * 8;
    const int arow1 = s1 * 16 + (lane & 7) + ((lane >> 3) & 1) * 8;
    const uint32_t a_kb0 = ((lane >> 4) & 1) * 16;
    const uint32_t a_off0 = (uint32_t)arow0 * 128;
    const uint32_t a_off1 = (uint32_t)arow1 * 128;
    const uint32_t a_xr0  = (uint32_t)(arow0 & 7) << 4;
    const uint32_t a_xr1  = (uint32_t)(arow1 & 7) << 4;
    const int browl = (lane & 7) + ((lane >> 4) & 1) * 8;
    const uint32_t b_rb  = (uint32_t)browl * 128 + (uint32_t)grp * 4096;
    const uint32_t b_xr  = (uint32_t)(lane & 7) << 4;
    const uint32_t b_kb0 = ((lane >> 3) & 1) * 16;

    float d[2][4][4];
#pragma unroll
    for (int s = 0; s < 2; s++)
#pragma unroll
        for (int i = 0; i < 4; i++)
#pragma unroll
            for (int j = 0; j < 4; j++) d[s][i][j] = 0.0f;

    float4 wr[8];
    const float4 z4 = make_float4(0.f, 0.f, 0.f, 0.f);

#define LOAD_W(TL) do {                                                      \
    const int kp_ = kbase + (TL) * KTILE + kq * 4;                           \
    const bool ok_ = (kp_ < NRED);                                           \
    const float* wp_ = W + (size_t)(m0 + wrp * 2 + row_off) * NRED + kp_;    \
    _Pragma("unroll")                                                        \
    for (int i = 0; i < 8; i++)                                              \
        wr[i] = ok_ ? *(const float4*)(wp_ + (size_t)16 * i * NRED) : z4;    \
} while (0)

#define ASYNC_B(TL, BUF) do {                                                \
    const __nv_bfloat16* src_ = g_B + (size_t)brow * KPAD                    \
                              + (kbase + (TL) * KTILE) + (bcol >> 1);        \
    const uint32_t db_ = sb + SM_B + (BUF) * SM_BSTG;                        \
    const uint32_t bo_ = (uint32_t)brow * 128 + bcol;                        \
    cpasync16(db_ + sw128(bo_),      src_);                                  \
    cpasync16(db_ + sw128(bo_ + 16), src_ + 8);                              \
    cpasync_commit();                                                        \
} while (0)

#define STS_A(BUF) do {                                                      \
    char* ab_ = smem + SM_A + (BUF) * SM_ASTG;                               \
    _Pragma("unroll")                                                        \
    for (int i = 0; i < 8; i++) {                                            \
        const int row_ = i * 16 + wrp * 2 + row_off;                         \
        const uint32_t sw_ = sw128((uint32_t)row_ * 128 + kq * 8);           \
        float4 f_ = wr[i];                                                   \
        __nv_bfloat16 h0,h1,h2,h3,l0,l1,l2,l3;                               \
        split2(f_.x, h0, l0); split2(f_.y, h1, l1);                          \
        split2(f_.z, h2, l2); split2(f_.w, h3, l3);                          \
        *(uint2*)(ab_ + sw_)         = make_uint2(packbf(h0,h1), packbf(h2,h3)); \
        *(uint2*)(ab_ + sw_ + 16384) = make_uint2(packbf(l0,l1), packbf(l2,l3)); \
    }                                                                        \
} while (0)

#define COMPUTE(BUF) do {                                                    \
    const uint32_t sa_ = sb + SM_A + (BUF) * SM_ASTG;                        \
    const uint32_t sB_ = sb + SM_B + (BUF) * SM_BSTG;                        \
    _Pragma("unroll")                                                        \
    for (int ks = 0; ks < 4; ks++) {                                         \
        uint32_t ah0[4], ah1[4], bf[2][4];                                   \
        const uint32_t kb_ = (uint32_t)(ks * 32) + a_kb0;                    \
        LDSM4(ah0, sa_ + a_off0 + (kb_ ^ a_xr0));                            \
        LDSM4(ah1, sa_ + a_off1 + (kb_ ^ a_xr1));                            \
        const uint32_t bkb_ = ((uint32_t)(ks * 32) + b_kb0) ^ b_xr;          \
        LDSM4(bf[0], sB_ + b_rb + bkb_);                                     \
        LDSM4(bf[1], sB_ + 2048 + b_rb + bkb_);                              \
        MMA16816(d[0][0], ah0, bf[0][0], bf[0][1]);                          \
        MMA16816(d[0][1], ah0, bf[0][2], bf[0][3]);                          \
        MMA16816(d[0][2], ah0, bf[1][0], bf[1][1]);                          \
        MMA16816(d[0][3], ah0, bf[1][2], bf[1][3]);                          \
        MMA16816(d[1][0], ah1, bf[0][0], bf[0][1]);                          \
        MMA16816(d[1][1], ah1, bf[0][2], bf[0][3]);                          \
        MMA16816(d[1][2], ah1, bf[1][0], bf[1][1]);                          \
        MMA16816(d[1][3], ah1, bf[1][2], bf[1][3]);                          \
        if (grp == 0) {                                                      \
            uint32_t al0[4], al1[4];                                         \
            LDSM4(al0, sa_ + 16384 + a_off0 + (kb_ ^ a_xr0));                \
            LDSM4(al1, sa_ + 16384 + a_off1 + (kb_ ^ a_xr1));                \
            MMA16816(d[0][0], al0, bf[0][0], bf[0][1]);                      \
            MMA16816(d[0][1], al0, bf[0][2], bf[0][3]);                      \
            MMA16816(d[0][2], al0, bf[1][0], bf[1][1]);                      \
            MMA16816(d[0][3], al0, bf[1][2], bf[1][3]);                      \
            MMA16816(d[1][0], al1, bf[0][0], bf[0][1]);                      \
            MMA16816(d[1][1], al1, bf[0][2], bf[0][3]);                      \
            MMA16816(d[1][2], al1, bf[1][0], bf[1][1]);                      \
            MMA16816(d[1][3], al1, bf[1][2], bf[1][3]);                      \
        }                                                                    \
    }                                                                        \
} while (0)

    ASYNC_B(0, 0);
    LOAD_W(0);
    STS_A(0);
    cpasync_wait0();
    __syncthreads();

    for (int tl = 0; tl < NT; tl++) {
        if (tl + 1 < NT) {
            ASYNC_B(tl + 1, (tl + 1) & 1);
            LOAD_W(tl + 1);
        }
        COMPUTE(tl & 1);
        if (tl + 1 < NT) {
            STS_A((tl + 1) & 1);
            cpasync_wait0();
            __syncthreads();
        }
    }

    __syncthreads();
    float* es = (float*)smem;
    const int eidx = (q * 32 + lane) * 33;
    if (grp == 1) {
#pragma unroll
        for (int s = 0; s < 2; s++)
#pragma unroll
            for (int i = 0; i < 4; i++)
#pragma unroll
                for (int j = 0; j < 4; j++)
                    es[eidx + s * 16 + i * 4 + j] = d[s][i][j];
    }
    __syncthreads();
    if (grp == 0) {
        float* gp = g_partial + (size_t)split * (TT * KFEAT) + m0;
        const int rbase = lane >> 2;
        const int c0 = (lane & 3) * 2;
#pragma unroll
        for (int s = 0; s < 2; s++) {
            const int feat = (2 * q + s) * 16 + rbase;
#pragma unroll
            for (int nt = 0; nt < 4; nt++) {
                const int t0 = nt * 8 + c0;
                float v0 = d[s][nt][0] + es[eidx + s * 16 + nt * 4 + 0];
                float v1 = d[s][nt][1] + es[eidx + s * 16 + nt * 4 + 1];
                float v2 = d[s][nt][2] + es[eidx + s * 16 + nt * 4 + 2];
                float v3 = d[s][nt][3] + es[eidx + s * 16 + nt * 4 + 3];
                gp[(size_t)t0 * KFEAT + feat]           = v0;
                gp[(size_t)(t0 + 1) * KFEAT + feat]     = v1;
                gp[(size_t)t0 * KFEAT + feat + 8]       = v2;
                gp[(size_t)(t0 + 1) * KFEAT + feat + 8] = v3;
            }
        }
    }
}

// ---------------------------------------------------------------------------
// Reduce partials across splits: g_dot[t][feat]
// ---------------------------------------------------------------------------
__global__ void __launch_bounds__(256)
reduce_kernel() {
    const int j = blockIdx.x * 256 + threadIdx.x;
    float s = 0.0f;
#pragma unroll 8
    for (int sp = 0; sp < SPLITS; sp++) s += g_partial[sp * (TT * KFEAT) + j];
    g_dot[j] = s;
}

// ---------------------------------------------------------------------------
// Selection (fused totals + k-WTA + output): 1 block x 512.
// Winners via bitonic sort of keys (total_bits<<32)|(511-k): descending key
// order == reference suppressive-argmax order (larger total first, ties ->
// smaller index). Top-16 keys with total>0 are winners. Exact & deterministic.
// ---------------------------------------------------------------------------
__global__ void __launch_bounds__(512, 1)
sel_kernel(float* __restrict__ out) {
    __shared__ unsigned long long key_s[KFEAT];
    __shared__ int   win_s[KFEAT];
    __shared__ float red_s[16];
    __shared__ float v_s;

    const int k = threadIdx.x;

    float pot[TT];
    int nspk = 0;
#pragma unroll
    for (int t = 0; t < TT; t++) {
        float dd = g_dot[t * KFEAT + k];
        pot[t] = dd;
        nspk += (dd > THRESH) ? 1 : 0;
    }
    int first = TT - nspk;
    if (first > TT - 1) first = TT - 1;
    if (first < 0) first = 0;
    float dv = g_dot[first * KFEAT + k];
    float value = (dv > THRESH) ? dv : 0.0f;
    float sval = (nspk > 0) ? value : 0.0f;

    float m = sval;
#pragma unroll
    for (int o = 16; o > 0; o >>= 1)
        m = fmaxf(m, __shfl_xor_sync(0xffffffffu, m, o));
    if ((k & 31) == 0) red_s[k >> 5] = m;
    win_s[k] = 0;
    __syncthreads();
    if (k == 0) {
        float mm = red_s[0];
#pragma unroll
        for (int i = 1; i < 16; i++) mm = fmaxf(mm, red_s[i]);
        v_s = mm * (float)TT;
    }
    __syncthreads();

    const float fns = (float)nspk;
    const float total = fns * value + fns * v_s;   // >= 0 always
    key_s[k] = ((unsigned long long)__float_as_uint(total) << 32)
             | (unsigned long long)(KFEAT - 1 - k);
    __syncthreads();

    // bitonic sort ascending (45 steps)
    for (int kk = 2; kk <= KFEAT; kk <<= 1) {
        for (int j = kk >> 1; j > 0; j >>= 1) {
            const int ixj = k ^ j;
            if (ixj > k) {
                unsigned long long a = key_s[k], b = key_s[ixj];
                const bool up = ((k & kk) == 0);
                if (up ? (a > b) : (a < b)) { key_s[k] = b; key_s[ixj] = a; }
            }
            __syncthreads();
        }
    }

    // top-16 = positions 496..511 (largest keys); mark winners with total>0
    if (k >= KFEAT - KWTA) {
        const unsigned long long key = key_s[k];
        if ((uint32_t)(key >> 32) != 0u) {
            const int idx = KFEAT - 1 - (int)(key & 0x1ffull);
            win_s[idx] = 1;
        }
    }
    __syncthreads();

    const bool win = (win_s[k] != 0);
#pragma unroll
    for (int t = 0; t < TT; t++)
        out[t * KFEAT + k] = (win && pot[t] > THRESH) ? 1.0f : 0.0f;
}

// ---------------------------------------------------------------------------
extern "C" void kernel_launch(void* const* d_in, const int* in_sizes, int n_in,
                              void* d_out, int out_size) {
    const float* a = (const float*)d_in[0];
    const float* b = (const float*)d_in[1];
    const float* rec = a;
    const float* wgt = b;
    if (in_sizes[0] > in_sizes[1]) { rec = b; wgt = a; }

    cudaFuncSetAttribute(gemm_kernel,
                         cudaFuncAttributeMaxDynamicSharedMemorySize, SMEMB);

    conv_kernel<<<(KPAD / 4 + 255) / 256, 256>>>(rec);
    dim3 grid(SPLITS, 4);
    gemm_kernel<<<grid, 256, SMEMB>>>(wgt);
    reduce_kernel<<<(TT * KFEAT) / 256, 256>>>();
    sel_kernel<<<1, 512>>>((float*)d_out);
}

// round 11
// speedup vs baseline: 1.1550x; 1.0349x over previous
#include <cuda_runtime.h>
#include <cuda_bf16.h>
#include <cstdint>

// ---------------------------------------------------------------------------
// Problem constants
#define NRED   100000
#define TT     32
#define KFEAT  512
#define THRESH 10.0f
#define KWTA   16

// GEMM tiling: 74 k-splits x 4 m-tiles = 296 CTAs (2 CTAs/SM)  [R7 proven]
#define SPLITS 74
#define KTILE  64
#define NT     22
#define CHUNK  (KTILE * NT)        // 1408
#define KPAD   (SPLITS * CHUNK)    // 104192
#define MTILE  128

#define SM_A    0
#define SM_ASTG 32768
#define SM_B    (2 * SM_ASTG)      // 65536
#define SM_BSTG 8192
#define SMEMB   (SM_B + 2 * SM_BSTG)   // 81920

// Device scratch (static — no dynamic allocation allowed)
__device__ __align__(128) __nv_bfloat16 g_B[(size_t)64 * KPAD];  // 13.3MB
__device__ float g_partial[SPLITS * TT * KFEAT];
__device__ float g_dot[TT * KFEAT];                // [t][feat]

typedef unsigned long long ull;

// ---------------------------------------------------------------------------
__device__ __forceinline__ uint32_t smem_u32(const void* p) {
    uint32_t a;
    asm("{ .reg .u64 t; cvta.to.shared.u64 t, %1; cvt.u32.u64 %0, t; }"
        : "=r"(a) : "l"(p));
    return a;
}
__device__ __forceinline__ uint32_t sw128(uint32_t off) {
    return off ^ ((off >> 3) & 0x70);
}
__device__ __forceinline__ uint32_t packbf(__nv_bfloat16 a, __nv_bfloat16 b) {
    __nv_bfloat162 v; v.x = a; v.y = b;
    return *reinterpret_cast<uint32_t*>(&v);
}
__device__ __forceinline__ void split2(float x, __nv_bfloat16& h, __nv_bfloat16& l) {
    h = __float2bfloat16(x);
    l = __float2bfloat16(x - __bfloat162float(h));
}
__device__ __forceinline__ void cpasync16(uint32_t dst, const void* src) {
    asm volatile("cp.async.cg.shared.global [%0], [%1], 16;"
                 :: "r"(dst), "l"(src) : "memory");
}
__device__ __forceinline__ void cpasync_commit() {
    asm volatile("cp.async.commit_group;" ::: "memory");
}
__device__ __forceinline__ void cpasync_wait0() {
    asm volatile("cp.async.wait_group 0;" ::: "memory");
}
#define LDSM4(R, ADDR)                                                        \
    asm volatile("ldmatrix.sync.aligned.m8n8.x4.shared.b16 {%0,%1,%2,%3}, [%4];" \
                 : "=r"((R)[0]), "=r"((R)[1]), "=r"((R)[2]), "=r"((R)[3])     \
                 : "r"(ADDR))
#define MMA16816(D, A, B0, B1)                                                \
    asm volatile("mma.sync.aligned.m16n8k16.row.col.f32.bf16.bf16.f32 "       \
                 "{%0,%1,%2,%3}, {%4,%5,%6,%7}, {%8,%9}, {%0,%1,%2,%3};"      \
                 : "+f"((D)[0]), "+f"((D)[1]), "+f"((D)[2]), "+f"((D)[3])     \
                 : "r"((A)[0]), "r"((A)[1]), "r"((A)[2]), "r"((A)[3]),        \
                   "r"(B0), "r"(B1))

// ---------------------------------------------------------------------------
// Split rec_field into bf16 hi/lo, zero-padded to KPAD
// ---------------------------------------------------------------------------
__global__ void __launch_bounds__(256)
conv_kernel(const float* __restrict__ R) {
    const int k4 = (blockIdx.x * 256 + threadIdx.x) * 4;
    if (k4 >= KPAD) return;
    const bool ok = (k4 < NRED);
#pragma unroll 4
    for (int t = 0; t < TT; t++) {
        float4 x = ok ? *(const float4*)(R + (size_t)t * NRED + k4)
                      : make_float4(0.f, 0.f, 0.f, 0.f);
        __nv_bfloat16 h0,h1,h2,h3,l0,l1,l2,l3;
        split2(x.x, h0, l0); split2(x.y, h1, l1);
        split2(x.z, h2, l2); split2(x.w, h3, l3);
        *(uint2*)(g_B + (size_t)t * KPAD + k4)        = make_uint2(packbf(h0,h1), packbf(h2,h3));
        *(uint2*)(g_B + (size_t)(t + 32) * KPAD + k4) = make_uint2(packbf(l0,l1), packbf(l2,l3));
    }
}

// ---------------------------------------------------------------------------
// GEMM: bf16 3-term split — EXACT R7 structure (best measured)
// ---------------------------------------------------------------------------
__global__ void __launch_bounds__(256, 2)
gemm_kernel(const float* __restrict__ W) {
    extern __shared__ char smem[];
    const uint32_t sb = smem_u32(smem);

    const int tid  = threadIdx.x;
    const int lane = tid & 31;
    const int wrp  = tid >> 5;
    const int q    = wrp & 3;
    const int grp  = wrp >> 2;
    const int split = blockIdx.x;
    const int m0    = blockIdx.y * MTILE;
    const int kbase = split * CHUNK;

    const int row_off = lane >> 4;
    const int kq      = lane & 15;
    const int brow = tid >> 2;
    const uint32_t bcol = (uint32_t)(tid & 3) * 32;

    const int s0 = 2 * q, s1 = 2 * q + 1;
    const int arow0 = s0 * 16 + (lane & 7) + ((lane >> 3) & 1) * 8;
    const int arow1 = s1 * 16 + (lane & 7) + ((lane >> 3) & 1) * 8;
    const uint32_t a_kb0 = ((lane >> 4) & 1) * 16;
    const uint32_t a_off0 = (uint32_t)arow0 * 128;
    const uint32_t a_off1 = (uint32_t)arow1 * 128;
    const uint32_t a_xr0  = (uint32_t)(arow0 & 7) << 4;
    const uint32_t a_xr1  = (uint32_t)(arow1 & 7) << 4;
    const int browl = (lane & 7) + ((lane >> 4) & 1) * 8;
    const uint32_t b_rb  = (uint32_t)browl * 128 + (uint32_t)grp * 4096;
    const uint32_t b_xr  = (uint32_t)(lane & 7) << 4;
    const uint32_t b_kb0 = ((lane >> 3) & 1) * 16;

    float d[2][4][4];
#pragma unroll
    for (int s = 0; s < 2; s++)
#pragma unroll
        for (int i = 0; i < 4; i++)
#pragma unroll
            for (int j = 0; j < 4; j++) d[s][i][j] = 0.0f;

    float4 wr[8];
    const float4 z4 = make_float4(0.f, 0.f, 0.f, 0.f);

#define LOAD_W(TL) do {                                                      \
    const int kp_ = kbase + (TL) * KTILE + kq * 4;                           \
    const bool ok_ = (kp_ < NRED);                                           \
    const float* wp_ = W + (size_t)(m0 + wrp * 2 + row_off) * NRED + kp_;    \
    _Pragma("unroll")                                                        \
    for (int i = 0; i < 8; i++)                                              \
        wr[i] = ok_ ? *(const float4*)(wp_ + (size_t)16 * i * NRED) : z4;    \
} while (0)

#define ASYNC_B(TL, BUF) do {                                                \
    const __nv_bfloat16* src_ = g_B + (size_t)brow * KPAD                    \
                              + (kbase + (TL) * KTILE) + (bcol >> 1);        \
    const uint32_t db_ = sb + SM_B + (BUF) * SM_BSTG;                        \
    const uint32_t bo_ = (uint32_t)brow * 128 + bcol;                        \
    cpasync16(db_ + sw128(bo_),      src_);                                  \
    cpasync16(db_ + sw128(bo_ + 16), src_ + 8);                              \
    cpasync_commit();                                                        \
} while (0)

#define STS_A(BUF) do {                                                      \
    char* ab_ = smem + SM_A + (BUF) * SM_ASTG;                               \
    _Pragma("unroll")                                                        \
    for (int i = 0; i < 8; i++) {                                            \
        const int row_ = i * 16 + wrp * 2 + row_off;                         \
        const uint32_t sw_ = sw128((uint32_t)row_ * 128 + kq * 8);           \
        float4 f_ = wr[i];                                                   \
        __nv_bfloat16 h0,h1,h2,h3,l0,l1,l2,l3;                               \
        split2(f_.x, h0, l0); split2(f_.y, h1, l1);                          \
        split2(f_.z, h2, l2); split2(f_.w, h3, l3);                          \
        *(uint2*)(ab_ + sw_)         = make_uint2(packbf(h0,h1), packbf(h2,h3)); \
        *(uint2*)(ab_ + sw_ + 16384) = make_uint2(packbf(l0,l1), packbf(l2,l3)); \
    }                                                                        \
} while (0)

#define COMPUTE(BUF) do {                                                    \
    const uint32_t sa_ = sb + SM_A + (BUF) * SM_ASTG;                        \
    const uint32_t sB_ = sb + SM_B + (BUF) * SM_BSTG;                        \
    _Pragma("unroll")                                                        \
    for (int ks = 0; ks < 4; ks++) {                                         \
        uint32_t ah0[4], ah1[4], bf[2][4];                                   \
        const uint32_t kb_ = (uint32_t)(ks * 32) + a_kb0;                    \
        LDSM4(ah0, sa_ + a_off0 + (kb_ ^ a_xr0));                            \
        LDSM4(ah1, sa_ + a_off1 + (kb_ ^ a_xr1));                            \
        const uint32_t bkb_ = ((uint32_t)(ks * 32) + b_kb0) ^ b_xr;          \
        LDSM4(bf[0], sB_ + b_rb + bkb_);                                     \
        LDSM4(bf[1], sB_ + 2048 + b_rb + bkb_);                              \
        MMA16816(d[0][0], ah0, bf[0][0], bf[0][1]);                          \
        MMA16816(d[0][1], ah0, bf[0][2], bf[0][3]);                          \
        MMA16816(d[0][2], ah0, bf[1][0], bf[1][1]);                          \
        MMA16816(d[0][3], ah0, bf[1][2], bf[1][3]);                          \
        MMA16816(d[1][0], ah1, bf[0][0], bf[0][1]);                          \
        MMA16816(d[1][1], ah1, bf[0][2], bf[0][3]);                          \
        MMA16816(d[1][2], ah1, bf[1][0], bf[1][1]);                          \
        MMA16816(d[1][3], ah1, bf[1][2], bf[1][3]);                          \
        if (grp == 0) {                                                      \
            uint32_t al0[4], al1[4];                                         \
            LDSM4(al0, sa_ + 16384 + a_off0 + (kb_ ^ a_xr0));                \
            LDSM4(al1, sa_ + 16384 + a_off1 + (kb_ ^ a_xr1));                \
            MMA16816(d[0][0], al0, bf[0][0], bf[0][1]);                      \
            MMA16816(d[0][1], al0, bf[0][2], bf[0][3]);                      \
            MMA16816(d[0][2], al0, bf[1][0], bf[1][1]);                      \
            MMA16816(d[0][3], al0, bf[1][2], bf[1][3]);                      \
            MMA16816(d[1][0], al1, bf[0][0], bf[0][1]);                      \
            MMA16816(d[1][1], al1, bf[0][2], bf[0][3]);                      \
            MMA16816(d[1][2], al1, bf[1][0], bf[1][1]);                      \
            MMA16816(d[1][3], al1, bf[1][2], bf[1][3]);                      \
        }                                                                    \
    }                                                                        \
} while (0)

    ASYNC_B(0, 0);
    LOAD_W(0);
    STS_A(0);
    cpasync_wait0();
    __syncthreads();

    for (int tl = 0; tl < NT; tl++) {
        if (tl + 1 < NT) {
            ASYNC_B(tl + 1, (tl + 1) & 1);
            LOAD_W(tl + 1);
        }
        COMPUTE(tl & 1);
        if (tl + 1 < NT) {
            STS_A((tl + 1) & 1);
            cpasync_wait0();
            __syncthreads();
        }
    }

    __syncthreads();
    float* es = (float*)smem;
    const int eidx = (q * 32 + lane) * 33;
    if (grp == 1) {
#pragma unroll
        for (int s = 0; s < 2; s++)
#pragma unroll
            for (int i = 0; i < 4; i++)
#pragma unroll
                for (int j = 0; j < 4; j++)
                    es[eidx + s * 16 + i * 4 + j] = d[s][i][j];
    }
    __syncthreads();
    if (grp == 0) {
        float* gp = g_partial + (size_t)split * (TT * KFEAT) + m0;
        const int rbase = lane >> 2;
        const int c0 = (lane & 3) * 2;
#pragma unroll
        for (int s = 0; s < 2; s++) {
            const int feat = (2 * q + s) * 16 + rbase;
#pragma unroll
            for (int nt = 0; nt < 4; nt++) {
                const int t0 = nt * 8 + c0;
                float v0 = d[s][nt][0] + es[eidx + s * 16 + nt * 4 + 0];
                float v1 = d[s][nt][1] + es[eidx + s * 16 + nt * 4 + 1];
                float v2 = d[s][nt][2] + es[eidx + s * 16 + nt * 4 + 2];
                float v3 = d[s][nt][3] + es[eidx + s * 16 + nt * 4 + 3];
                gp[(size_t)t0 * KFEAT + feat]           = v0;
                gp[(size_t)(t0 + 1) * KFEAT + feat]     = v1;
                gp[(size_t)t0 * KFEAT + feat + 8]       = v2;
                gp[(size_t)(t0 + 1) * KFEAT + feat + 8] = v3;
            }
        }
    }
}

// ---------------------------------------------------------------------------
// Reduce partials across splits: g_dot[t][feat]
// ---------------------------------------------------------------------------
__global__ void __launch_bounds__(256)
reduce_kernel() {
    const int j = blockIdx.x * 256 + threadIdx.x;
    float s = 0.0f;
#pragma unroll 8
    for (int sp = 0; sp < SPLITS; sp++) s += g_partial[sp * (TT * KFEAT) + j];
    g_dot[j] = s;
}

// ---------------------------------------------------------------------------
// Selection: fused totals + k-WTA + output. 1 block x 512.
// Hybrid bitonic sort: intra-warp stages (j<=16) via shfl in registers
// (no barriers), cross-warp stages (j>=32) via smem (2 barriers each).
// Descending key order == reference suppressive-argmax order.
// ---------------------------------------------------------------------------
__global__ void __launch_bounds__(512, 1)
sel_kernel(float* __restrict__ out) {
    __shared__ ull   key_s[KFEAT];
    __shared__ int   win_s[KFEAT];
    __shared__ float red_s[16];
    __shared__ float v_s;

    const int k = threadIdx.x;

    float pot[TT];
    int nspk = 0;
#pragma unroll
    for (int t = 0; t < TT; t++) {
        float dd = g_dot[t * KFEAT + k];
        pot[t] = dd;
        nspk += (dd > THRESH) ? 1 : 0;
    }
    int first = TT - nspk;
    if (first > TT - 1) first = TT - 1;
    if (first < 0) first = 0;
    float dv = g_dot[first * KFEAT + k];
    float value = (dv > THRESH) ? dv : 0.0f;
    float sval = (nspk > 0) ? value : 0.0f;

    float m = sval;
#pragma unroll
    for (int o = 16; o > 0; o >>= 1)
        m = fmaxf(m, __shfl_xor_sync(0xffffffffu, m, o));
    if ((k & 31) == 0) red_s[k >> 5] = m;
    win_s[k] = 0;
    __syncthreads();
    if (k == 0) {
        float mm = red_s[0];
#pragma unroll
        for (int i = 1; i < 16; i++) mm = fmaxf(mm, red_s[i]);
        v_s = mm * (float)TT;
    }
    __syncthreads();

    const float fns = (float)nspk;
    const float total = fns * value + fns * v_s;   // >= 0 always
    ull key = ((ull)__float_as_uint(total) << 32)
            | (ull)(KFEAT - 1 - k);

    // ---- hybrid bitonic sort (ascending), key register-resident ----
#define INTRA_STAGE(KK, J) do {                                              \
    ull other_ = __shfl_xor_sync(0xffffffffu, key, (J));                     \
    const bool up_ = ((k & (KK)) == 0);                                      \
    const bool lo_ = ((k & (J)) == 0);                                       \
    const bool keepmin_ = (up_ == lo_);                                      \
    key = keepmin_ ? (key < other_ ? key : other_)                           \
                   : (key > other_ ? key : other_);                          \
} while (0)

#define CROSS_STAGE(KK, J) do {                                              \
    key_s[k] = key;                                                          \
    __syncthreads();                                                         \
    ull other_ = key_s[k ^ (J)];                                             \
    const bool up_ = ((k & (KK)) == 0);                                      \
    const bool lo_ = ((k & (J)) == 0);                                       \
    const bool keepmin_ = (up_ == lo_);                                      \
    key = keepmin_ ? (key < other_ ? key : other_)                           \
                   : (key > other_ ? key : other_);                          \
    __syncthreads();                                                         \
} while (0)

    // kk = 2..32: fully intra-warp
    INTRA_STAGE(2, 1);
    INTRA_STAGE(4, 2);  INTRA_STAGE(4, 1);
    INTRA_STAGE(8, 4);  INTRA_STAGE(8, 2);  INTRA_STAGE(8, 1);
    INTRA_STAGE(16, 8); INTRA_STAGE(16, 4); INTRA_STAGE(16, 2); INTRA_STAGE(16, 1);
    INTRA_STAGE(32, 16); INTRA_STAGE(32, 8); INTRA_STAGE(32, 4);
    INTRA_STAGE(32, 2);  INTRA_STAGE(32, 1);
    // kk = 64
    CROSS_STAGE(64, 32);
    INTRA_STAGE(64, 16); INTRA_STAGE(64, 8); INTRA_STAGE(64, 4);
    INTRA_STAGE(64, 2);  INTRA_STAGE(64, 1);
    // kk = 128
    CROSS_STAGE(128, 64); CROSS_STAGE(128, 32);
    INTRA_STAGE(128, 16); INTRA_STAGE(128, 8); INTRA_STAGE(128, 4);
    INTRA_STAGE(128, 2);  INTRA_STAGE(128, 1);
    // kk = 256
    CROSS_STAGE(256, 128); CROSS_STAGE(256, 64); CROSS_STAGE(256, 32);
    INTRA_STAGE(256, 16); INTRA_STAGE(256, 8); INTRA_STAGE(256, 4);
    INTRA_STAGE(256, 2);  INTRA_STAGE(256, 1);
    // kk = 512
    CROSS_STAGE(512, 256); CROSS_STAGE(512, 128); CROSS_STAGE(512, 64);
    CROSS_STAGE(512, 32);
    INTRA_STAGE(512, 16); INTRA_STAGE(512, 8); INTRA_STAGE(512, 4);
    INTRA_STAGE(512, 2);  INTRA_STAGE(512, 1);

    // thread k now holds sorted element k (ascending). Top-16 in k>=496.
    if (k >= KFEAT - KWTA) {
        if ((uint32_t)(key >> 32) != 0u) {
            const int idx = KFEAT - 1 - (int)(key & 0x1ffull);
            win_s[idx] = 1;
        }
    }
    __syncthreads();

    const bool win = (win_s[k] != 0);
#pragma unroll
    for (int t = 0; t < TT; t++)
        out[t * KFEAT + k] = (win && pot[t] > THRESH) ? 1.0f : 0.0f;
}

// ---------------------------------------------------------------------------
extern "C" void kernel_launch(void* const* d_in, const int* in_sizes, int n_in,
                              void* d_out, int out_size) {
    const float* a = (const float*)d_in[0];
    const float* b = (const float*)d_in[1];
    const float* rec = a;
    const float* wgt = b;
    if (in_sizes[0] > in_sizes[1]) { rec = b; wgt = a; }

    cudaFuncSetAttribute(gemm_kernel,
                         cudaFuncAttributeMaxDynamicSharedMemorySize, SMEMB);

    conv_kernel<<<(KPAD / 4 + 255) / 256, 256>>>(rec);
    dim3 grid(SPLITS, 4);
    gemm_kernel<<<grid, 256, SMEMB>>>(wgt);
    reduce_kernel<<<(TT * KFEAT) / 256, 256>>>();
    sel_kernel<<<1, 512>>>((float*)d_out);
}

// round 12
// speedup vs baseline: 1.1556x; 1.0005x over previous
#include <cuda_runtime.h>
#include <cuda_bf16.h>
#include <cstdint>

// ---------------------------------------------------------------------------
// Problem constants
#define NRED   100000
#define TT     32
#define KFEAT  512
#define THRESH 10.0f
#define KWTA   16

// GEMM tiling: 74 k-splits x 4 m-tiles = 296 CTAs (2 CTAs/SM)  [R7 proven]
#define SPLITS 74
#define KTILE  64
#define NT     22
#define CHUNK  (KTILE * NT)        // 1408
#define KPAD   (SPLITS * CHUNK)    // 104192
#define MTILE  128

#define SM_A    0
#define SM_ASTG 32768
#define SM_B    (2 * SM_ASTG)      // 65536
#define SM_BSTG 8192
#define SMEMB   (SM_B + 2 * SM_BSTG)   // 81920

#define RS_BLOCKS 32               // reduce_sel grid

// Device scratch (static — no dynamic allocation allowed)
__device__ __align__(128) __nv_bfloat16 g_B[(size_t)64 * KPAD];  // 13.3MB
__device__ float g_partial[SPLITS * TT * KFEAT];
__device__ float g_dot[TT * KFEAT];                // [t][feat]
__device__ int   g_arrive;                         // last-block counter

typedef unsigned long long ull;

// ---------------------------------------------------------------------------
__device__ __forceinline__ uint32_t smem_u32(const void* p) {
    uint32_t a;
    asm("{ .reg .u64 t; cvta.to.shared.u64 t, %1; cvt.u32.u64 %0, t; }"
        : "=r"(a) : "l"(p));
    return a;
}
__device__ __forceinline__ uint32_t sw128(uint32_t off) {
    return off ^ ((off >> 3) & 0x70);
}
__device__ __forceinline__ uint32_t packbf(__nv_bfloat16 a, __nv_bfloat16 b) {
    __nv_bfloat162 v; v.x = a; v.y = b;
    return *reinterpret_cast<uint32_t*>(&v);
}
__device__ __forceinline__ void split2(float x, __nv_bfloat16& h, __nv_bfloat16& l) {
    h = __float2bfloat16(x);
    l = __float2bfloat16(x - __bfloat162float(h));
}
__device__ __forceinline__ void cpasync16(uint32_t dst, const void* src) {
    asm volatile("cp.async.cg.shared.global [%0], [%1], 16;"
                 :: "r"(dst), "l"(src) : "memory");
}
__device__ __forceinline__ void cpasync_commit() {
    asm volatile("cp.async.commit_group;" ::: "memory");
}
__device__ __forceinline__ void cpasync_wait0() {
    asm volatile("cp.async.wait_group 0;" ::: "memory");
}
#define LDSM4(R, ADDR)                                                        \
    asm volatile("ldmatrix.sync.aligned.m8n8.x4.shared.b16 {%0,%1,%2,%3}, [%4];" \
                 : "=r"((R)[0]), "=r"((R)[1]), "=r"((R)[2]), "=r"((R)[3])     \
                 : "r"(ADDR))
#define MMA16816(D, A, B0, B1)                                                \
    asm volatile("mma.sync.aligned.m16n8k16.row.col.f32.bf16.bf16.f32 "       \
                 "{%0,%1,%2,%3}, {%4,%5,%6,%7}, {%8,%9}, {%0,%1,%2,%3};"      \
                 : "+f"((D)[0]), "+f"((D)[1]), "+f"((D)[2]), "+f"((D)[3])     \
                 : "r"((A)[0]), "r"((A)[1]), "r"((A)[2]), "r"((A)[3]),        \
                   "r"(B0), "r"(B1))

// ---------------------------------------------------------------------------
// Split rec_field into bf16 hi/lo, zero-padded to KPAD. Also resets the
// last-block arrival counter for this graph replay (stream-ordered before
// reduce_sel_kernel).
// ---------------------------------------------------------------------------
__global__ void __launch_bounds__(256)
conv_kernel(const float* __restrict__ R) {
    if (blockIdx.x == 0 && threadIdx.x == 0) g_arrive = 0;
    const int k4 = (blockIdx.x * 256 + threadIdx.x) * 4;
    if (k4 >= KPAD) return;
    const bool ok = (k4 < NRED);
#pragma unroll 4
    for (int t = 0; t < TT; t++) {
        float4 x = ok ? *(const float4*)(R + (size_t)t * NRED + k4)
                      : make_float4(0.f, 0.f, 0.f, 0.f);
        __nv_bfloat16 h0,h1,h2,h3,l0,l1,l2,l3;
        split2(x.x, h0, l0); split2(x.y, h1, l1);
        split2(x.z, h2, l2); split2(x.w, h3, l3);
        *(uint2*)(g_B + (size_t)t * KPAD + k4)        = make_uint2(packbf(h0,h1), packbf(h2,h3));
        *(uint2*)(g_B + (size_t)(t + 32) * KPAD + k4) = make_uint2(packbf(l0,l1), packbf(l2,l3));
    }
}

// ---------------------------------------------------------------------------
// GEMM: bf16 3-term split — EXACT R7 structure (best measured)
// ---------------------------------------------------------------------------
__global__ void __launch_bounds__(256, 2)
gemm_kernel(const float* __restrict__ W) {
    extern __shared__ char smem[];
    const uint32_t sb = smem_u32(smem);

    const int tid  = threadIdx.x;
    const int lane = tid & 31;
    const int wrp  = tid >> 5;
    const int q    = wrp & 3;
    const int grp  = wrp >> 2;
    const int split = blockIdx.x;
    const int m0    = blockIdx.y * MTILE;
    const int kbase = split * CHUNK;

    const int row_off = lane >> 4;
    const int kq      = lane & 15;
    const int brow = tid >> 2;
    const uint32_t bcol = (uint32_t)(tid & 3) * 32;

    const int s0 = 2 * q, s1 = 2 * q + 1;
    const int arow0 = s0 * 16 + (lane & 7) + ((lane >> 3) & 1) * 8;
    const int arow1 = s1 * 16 + (lane & 7) + ((lane >> 3) & 1) * 8;
    const uint32_t a_kb0 = ((lane >> 4) & 1) * 16;
    const uint32_t a_off0 = (uint32_t)arow0 * 128;
    const uint32_t a_off1 = (uint32_t)arow1 * 128;
    const uint32_t a_xr0  = (uint32_t)(arow0 & 7) << 4;
    const uint32_t a_xr1  = (uint32_t)(arow1 & 7) << 4;
    const int browl = (lane & 7) + ((lane >> 4) & 1) * 8;
    const uint32_t b_rb  = (uint32_t)browl * 128 + (uint32_t)grp * 4096;
    const uint32_t b_xr  = (uint32_t)(lane & 7) << 4;
    const uint32_t b_kb0 = ((lane >> 3) & 1) * 16;

    float d[2][4][4];
#pragma unroll
    for (int s = 0; s < 2; s++)
#pragma unroll
        for (int i = 0; i < 4; i++)
#pragma unroll
            for (int j = 0; j < 4; j++) d[s][i][j] = 0.0f;

    float4 wr[8];
    const float4 z4 = make_float4(0.f, 0.f, 0.f, 0.f);

#define LOAD_W(TL) do {                                                      \
    const int kp_ = kbase + (TL) * KTILE + kq * 4;                           \
    const bool ok_ = (kp_ < NRED);                                           \
    const float* wp_ = W + (size_t)(m0 + wrp * 2 + row_off) * NRED + kp_;    \
    _Pragma("unroll")                                                        \
    for (int i = 0; i < 8; i++)                                              \
        wr[i] = ok_ ? *(const float4*)(wp_ + (size_t)16 * i * NRED) : z4;    \
} while (0)

#define ASYNC_B(TL, BUF) do {                                                \
    const __nv_bfloat16* src_ = g_B + (size_t)brow * KPAD                    \
                              + (kbase + (TL) * KTILE) + (bcol >> 1);        \
    const uint32_t db_ = sb + SM_B + (BUF) * SM_BSTG;                        \
    const uint32_t bo_ = (uint32_t)brow * 128 + bcol;                        \
    cpasync16(db_ + sw128(bo_),      src_);                                  \
    cpasync16(db_ + sw128(bo_ + 16), src_ + 8);                              \
    cpasync_commit();                                                        \
} while (0)

#define STS_A(BUF) do {                                                      \
    char* ab_ = smem + SM_A + (BUF) * SM_ASTG;                               \
    _Pragma("unroll")                                                        \
    for (int i = 0; i < 8; i++) {                                            \
        const int row_ = i * 16 + wrp * 2 + row_off;                         \
        const uint32_t sw_ = sw128((uint32_t)row_ * 128 + kq * 8);           \
        float4 f_ = wr[i];                                                   \
        __nv_bfloat16 h0,h1,h2,h3,l0,l1,l2,l3;                               \
        split2(f_.x, h0, l0); split2(f_.y, h1, l1);                          \
        split2(f_.z, h2, l2); split2(f_.w, h3, l3);                          \
        *(uint2*)(ab_ + sw_)         = make_uint2(packbf(h0,h1), packbf(h2,h3)); \
        *(uint2*)(ab_ + sw_ + 16384) = make_uint2(packbf(l0,l1), packbf(l2,l3)); \
    }                                                                        \
} while (0)

#define COMPUTE(BUF) do {                                                    \
    const uint32_t sa_ = sb + SM_A + (BUF) * SM_ASTG;                        \
    const uint32_t sB_ = sb + SM_B + (BUF) * SM_BSTG;                        \
    _Pragma("unroll")                                                        \
    for (int ks = 0; ks < 4; ks++) {                                         \
        uint32_t ah0[4], ah1[4], bf[2][4];                                   \
        const uint32_t kb_ = (uint32_t)(ks * 32) + a_kb0;                    \
        LDSM4(ah0, sa_ + a_off0 + (kb_ ^ a_xr0));                            \
        LDSM4(ah1, sa_ + a_off1 + (kb_ ^ a_xr1));                            \
        const uint32_t bkb_ = ((uint32_t)(ks * 32) + b_kb0) ^ b_xr;          \
        LDSM4(bf[0], sB_ + b_rb + bkb_);                                     \
        LDSM4(bf[1], sB_ + 2048 + b_rb + bkb_);                              \
        MMA16816(d[0][0], ah0, bf[0][0], bf[0][1]);                          \
        MMA16816(d[0][1], ah0, bf[0][2], bf[0][3]);                          \
        MMA16816(d[0][2], ah0, bf[1][0], bf[1][1]);                          \
        MMA16816(d[0][3], ah0, bf[1][2], bf[1][3]);                          \
        MMA16816(d[1][0], ah1, bf[0][0], bf[0][1]);                          \
        MMA16816(d[1][1], ah1, bf[0][2], bf[0][3]);                          \
        MMA16816(d[1][2], ah1, bf[1][0], bf[1][1]);                          \
        MMA16816(d[1][3], ah1, bf[1][2], bf[1][3]);                          \
        if (grp == 0) {                                                      \
            uint32_t al0[4], al1[4];                                         \
            LDSM4(al0, sa_ + 16384 + a_off0 + (kb_ ^ a_xr0));                \
            LDSM4(al1, sa_ + 16384 + a_off1 + (kb_ ^ a_xr1));                \
            MMA16816(d[0][0], al0, bf[0][0], bf[0][1]);                      \
            MMA16816(d[0][1], al0, bf[0][2], bf[0][3]);                      \
            MMA16816(d[0][2], al0, bf[1][0], bf[1][1]);                      \
            MMA16816(d[0][3], al0, bf[1][2], bf[1][3]);                      \
            MMA16816(d[1][0], al1, bf[0][0], bf[0][1]);                      \
            MMA16816(d[1][1], al1, bf[0][2], bf[0][3]);                      \
            MMA16816(d[1][2], al1, bf[1][0], bf[1][1]);                      \
            MMA16816(d[1][3], al1, bf[1][2], bf[1][3]);                      \
        }                                                                    \
    }                                                                        \
} while (0)

    ASYNC_B(0, 0);
    LOAD_W(0);
    STS_A(0);
    cpasync_wait0();
    __syncthreads();

    for (int tl = 0; tl < NT; tl++) {
        if (tl + 1 < NT) {
            ASYNC_B(tl + 1, (tl + 1) & 1);
            LOAD_W(tl + 1);
        }
        COMPUTE(tl & 1);
        if (tl + 1 < NT) {
            STS_A((tl + 1) & 1);
            cpasync_wait0();
            __syncthreads();
        }
    }

    __syncthreads();
    float* es = (float*)smem;
    const int eidx = (q * 32 + lane) * 33;
    if (grp == 1) {
#pragma unroll
        for (int s = 0; s < 2; s++)
#pragma unroll
            for (int i = 0; i < 4; i++)
#pragma unroll
                for (int j = 0; j < 4; j++)
                    es[eidx + s * 16 + i * 4 + j] = d[s][i][j];
    }
    __syncthreads();
    if (grp == 0) {
        float* gp = g_partial + (size_t)split * (TT * KFEAT) + m0;
        const int rbase = lane >> 2;
        const int c0 = (lane & 3) * 2;
#pragma unroll
        for (int s = 0; s < 2; s++) {
            const int feat = (2 * q + s) * 16 + rbase;
#pragma unroll
            for (int nt = 0; nt < 4; nt++) {
                const int t0 = nt * 8 + c0;
                float v0 = d[s][nt][0] + es[eidx + s * 16 + nt * 4 + 0];
                float v1 = d[s][nt][1] + es[eidx + s * 16 + nt * 4 + 1];
                float v2 = d[s][nt][2] + es[eidx + s * 16 + nt * 4 + 2];
                float v3 = d[s][nt][3] + es[eidx + s * 16 + nt * 4 + 3];
                gp[(size_t)t0 * KFEAT + feat]           = v0;
                gp[(size_t)(t0 + 1) * KFEAT + feat]     = v1;
                gp[(size_t)t0 * KFEAT + feat + 8]       = v2;
                gp[(size_t)(t0 + 1) * KFEAT + feat + 8] = v3;
            }
        }
    }
}

// ---------------------------------------------------------------------------
// Fused reduce + selection. 32 blocks x 512 threads.
// Phase 1 (all blocks): g_dot[j] = sum over splits (1 element per thread).
// Phase 2 (last-arriving block only): exact reference totals + k-WTA via
// hybrid bitonic sort + output. Output independent of which block is last.
// ---------------------------------------------------------------------------
__global__ void __launch_bounds__(512, 1)
reduce_sel_kernel(float* __restrict__ out) {
    const int k = threadIdx.x;
    {
        const int j = blockIdx.x * 512 + k;
        float s = 0.0f;
#pragma unroll 8
        for (int sp = 0; sp < SPLITS; sp++) s += g_partial[sp * (TT * KFEAT) + j];
        g_dot[j] = s;
    }

    // last-block election (threadfenceReduction pattern)
    __shared__ int is_last;
    __threadfence();
    __syncthreads();
    if (k == 0) is_last = (atomicAdd(&g_arrive, 1) == RS_BLOCKS - 1);
    __syncthreads();
    if (!is_last) return;
    __threadfence();

    // ---- selection phase (this block only) ----
    __shared__ ull   key_s[KFEAT];
    __shared__ int   win_s[KFEAT];
    __shared__ float red_s[16];
    __shared__ float v_s;

    float pot[TT];
    int nspk = 0;
#pragma unroll
    for (int t = 0; t < TT; t++) {
        float dd = g_dot[t * KFEAT + k];
        pot[t] = dd;
        nspk += (dd > THRESH) ? 1 : 0;
    }
    int first = TT - nspk;
    if (first > TT - 1) first = TT - 1;
    if (first < 0) first = 0;
    float dv = g_dot[first * KFEAT + k];
    float value = (dv > THRESH) ? dv : 0.0f;
    float sval = (nspk > 0) ? value : 0.0f;

    float m = sval;
#pragma unroll
    for (int o = 16; o > 0; o >>= 1)
        m = fmaxf(m, __shfl_xor_sync(0xffffffffu, m, o));
    if ((k & 31) == 0) red_s[k >> 5] = m;
    win_s[k] = 0;
    __syncthreads();
    if (k == 0) {
        float mm = red_s[0];
#pragma unroll
        for (int i = 1; i < 16; i++) mm = fmaxf(mm, red_s[i]);
        v_s = mm * (float)TT;
    }
    __syncthreads();

    const float fns = (float)nspk;
    const float total = fns * value + fns * v_s;   // >= 0 always
    ull key = ((ull)__float_as_uint(total) << 32)
            | (ull)(KFEAT - 1 - k);

#define INTRA_STAGE(KK, J) do {                                              \
    ull other_ = __shfl_xor_sync(0xffffffffu, key, (J));                     \
    const bool up_ = ((k & (KK)) == 0);                                      \
    const bool lo_ = ((k & (J)) == 0);                                       \
    const bool keepmin_ = (up_ == lo_);                                      \
    key = keepmin_ ? (key < other_ ? key : other_)                           \
                   : (key > other_ ? key : other_);                          \
} while (0)

#define CROSS_STAGE(KK, J) do {                                              \
    key_s[k] = key;                                                          \
    __syncthreads();                                                         \
    ull other_ = key_s[k ^ (J)];                                             \
    const bool up_ = ((k & (KK)) == 0);                                      \
    const bool lo_ = ((k & (J)) == 0);                                       \
    const bool keepmin_ = (up_ == lo_);                                      \
    key = keepmin_ ? (key < other_ ? key : other_)                           \
                   : (key > other_ ? key : other_);                          \
    __syncthreads();                                                         \
} while (0)

    INTRA_STAGE(2, 1);
    INTRA_STAGE(4, 2);  INTRA_STAGE(4, 1);
    INTRA_STAGE(8, 4);  INTRA_STAGE(8, 2);  INTRA_STAGE(8, 1);
    INTRA_STAGE(16, 8); INTRA_STAGE(16, 4); INTRA_STAGE(16, 2); INTRA_STAGE(16, 1);
    INTRA_STAGE(32, 16); INTRA_STAGE(32, 8); INTRA_STAGE(32, 4);
    INTRA_STAGE(32, 2);  INTRA_STAGE(32, 1);
    CROSS_STAGE(64, 32);
    INTRA_STAGE(64, 16); INTRA_STAGE(64, 8); INTRA_STAGE(64, 4);
    INTRA_STAGE(64, 2);  INTRA_STAGE(64, 1);
    CROSS_STAGE(128, 64); CROSS_STAGE(128, 32);
    INTRA_STAGE(128, 16); INTRA_STAGE(128, 8); INTRA_STAGE(128, 4);
    INTRA_STAGE(128, 2);  INTRA_STAGE(128, 1);
    CROSS_STAGE(256, 128); CROSS_STAGE(256, 64); CROSS_STAGE(256, 32);
    INTRA_STAGE(256, 16); INTRA_STAGE(256, 8); INTRA_STAGE(256, 4);
    INTRA_STAGE(256, 2);  INTRA_STAGE(256, 1);
    CROSS_STAGE(512, 256); CROSS_STAGE(512, 128); CROSS_STAGE(512, 64);
    CROSS_STAGE(512, 32);
    INTRA_STAGE(512, 16); INTRA_STAGE(512, 8); INTRA_STAGE(512, 4);
    INTRA_STAGE(512, 2);  INTRA_STAGE(512, 1);

    if (k >= KFEAT - KWTA) {
        if ((uint32_t)(key >> 32) != 0u) {
            const int idx = KFEAT - 1 - (int)(key & 0x1ffull);
            win_s[idx] = 1;
        }
    }
    __syncthreads();

    const bool win = (win_s[k] != 0);
#pragma unroll
    for (int t = 0; t < TT; t++)
        out[t * KFEAT + k] = (win && pot[t] > THRESH) ? 1.0f : 0.0f;
}

// ---------------------------------------------------------------------------
extern "C" void kernel_launch(void* const* d_in, const int* in_sizes, int n_in,
                              void* d_out, int out_size) {
    const float* a = (const float*)d_in[0];
    const float* b = (const float*)d_in[1];
    const float* rec = a;
    const float* wgt = b;
    if (in_sizes[0] > in_sizes[1]) { rec = b; wgt = a; }

    cudaFuncSetAttribute(gemm_kernel,
                         cudaFuncAttributeMaxDynamicSharedMemorySize, SMEMB);

    conv_kernel<<<(KPAD / 4 + 255) / 256, 256>>>(rec);
    dim3 grid(SPLITS, 4);
    gemm_kernel<<<grid, 256, SMEMB>>>(wgt);
    reduce_sel_kernel<<<RS_BLOCKS, 512>>>((float*)d_out);
}

// round 13
// speedup vs baseline: 1.1986x; 1.0372x over previous
#include <cuda_runtime.h>
#include <cuda_bf16.h>
#include <cstdint>

// ---------------------------------------------------------------------------
// Problem constants
#define NRED   100000
#define TT     32
#define KFEAT  512
#define THRESH 10.0f
#define KWTA   16

// GEMM tiling: 74 k-splits x 4 m-tiles = 296 CTAs (2 CTAs/SM)  [R7 proven]
#define SPLITS 74
#define KTILE  64
#define NT     22
#define CHUNK  (KTILE * NT)        // 1408
#define KPAD   (SPLITS * CHUNK)    // 104192
#define MTILE  128

#define SM_A    0
#define SM_ASTG 32768
#define SM_B    (2 * SM_ASTG)      // 65536
#define SM_BSTG 8192
#define SMEMB   (SM_B + 2 * SM_BSTG)   // 81920

#define RS_BLOCKS 32               // reduce_sel grid

// Device scratch (static — no dynamic allocation allowed)
__device__ __align__(128) __nv_bfloat16 g_B[(size_t)64 * KPAD];  // 13.3MB
__device__ float g_partial[SPLITS * TT * KFEAT];
__device__ float g_dot[TT * KFEAT];                // [t][feat]
__device__ int   g_arrive;                         // last-block counter

typedef unsigned long long ull;

// ---------------------------------------------------------------------------
__device__ __forceinline__ uint32_t smem_u32(const void* p) {
    uint32_t a;
    asm("{ .reg .u64 t; cvta.to.shared.u64 t, %1; cvt.u32.u64 %0, t; }"
        : "=r"(a) : "l"(p));
    return a;
}
__device__ __forceinline__ uint32_t sw128(uint32_t off) {
    return off ^ ((off >> 3) & 0x70);
}
__device__ __forceinline__ uint32_t packbf(__nv_bfloat16 a, __nv_bfloat16 b) {
    __nv_bfloat162 v; v.x = a; v.y = b;
    return *reinterpret_cast<uint32_t*>(&v);
}
__device__ __forceinline__ void split2(float x, __nv_bfloat16& h, __nv_bfloat16& l) {
    h = __float2bfloat16(x);
    l = __float2bfloat16(x - __bfloat162float(h));
}
__device__ __forceinline__ void cpasync16(uint32_t dst, const void* src) {
    asm volatile("cp.async.cg.shared.global [%0], [%1], 16;"
                 :: "r"(dst), "l"(src) : "memory");
}
__device__ __forceinline__ void cpasync_commit() {
    asm volatile("cp.async.commit_group;" ::: "memory");
}
__device__ __forceinline__ void cpasync_wait0() {
    asm volatile("cp.async.wait_group 0;" ::: "memory");
}
#define LDSM4(R, ADDR)                                                        \
    asm volatile("ldmatrix.sync.aligned.m8n8.x4.shared.b16 {%0,%1,%2,%3}, [%4];" \
                 : "=r"((R)[0]), "=r"((R)[1]), "=r"((R)[2]), "=r"((R)[3])     \
                 : "r"(ADDR))
#define MMA16816(D, A, B0, B1)                                                \
    asm volatile("mma.sync.aligned.m16n8k16.row.col.f32.bf16.bf16.f32 "       \
                 "{%0,%1,%2,%3}, {%4,%5,%6,%7}, {%8,%9}, {%0,%1,%2,%3};"      \
                 : "+f"((D)[0]), "+f"((D)[1]), "+f"((D)[2]), "+f"((D)[3])     \
                 : "r"((A)[0]), "r"((A)[1]), "r"((A)[2]), "r"((A)[3]),        \
                   "r"(B0), "r"(B1))

// ---------------------------------------------------------------------------
// Split rec_field into bf16 hi/lo, zero-padded to KPAD. Parallel over (t, k):
// grid (102, 32), each thread: 1 LDG.128 -> 2 STG.64. Also resets g_arrive.
// ---------------------------------------------------------------------------
__global__ void __launch_bounds__(256)
conv_kernel(const float* __restrict__ R) {
    if (blockIdx.x == 0 && blockIdx.y == 0 && threadIdx.x == 0) g_arrive = 0;
    const int k4 = (blockIdx.x * 256 + threadIdx.x) * 4;
    if (k4 >= KPAD) return;
    const int t = blockIdx.y;
    float4 x = (k4 < NRED) ? *(const float4*)(R + (size_t)t * NRED + k4)
                           : make_float4(0.f, 0.f, 0.f, 0.f);
    __nv_bfloat16 h0,h1,h2,h3,l0,l1,l2,l3;
    split2(x.x, h0, l0); split2(x.y, h1, l1);
    split2(x.z, h2, l2); split2(x.w, h3, l3);
    *(uint2*)(g_B + (size_t)t * KPAD + k4)        = make_uint2(packbf(h0,h1), packbf(h2,h3));
    *(uint2*)(g_B + (size_t)(t + 32) * KPAD + k4) = make_uint2(packbf(l0,l1), packbf(l2,l3));
}

// ---------------------------------------------------------------------------
// GEMM: bf16 3-term split — EXACT R7 structure (best measured)
// ---------------------------------------------------------------------------
__global__ void __launch_bounds__(256, 2)
gemm_kernel(const float* __restrict__ W) {
    extern __shared__ char smem[];
    const uint32_t sb = smem_u32(smem);

    const int tid  = threadIdx.x;
    const int lane = tid & 31;
    const int wrp  = tid >> 5;
    const int q    = wrp & 3;
    const int grp  = wrp >> 2;
    const int split = blockIdx.x;
    const int m0    = blockIdx.y * MTILE;
    const int kbase = split * CHUNK;

    const int row_off = lane >> 4;
    const int kq      = lane & 15;
    const int brow = tid >> 2;
    const uint32_t bcol = (uint32_t)(tid & 3) * 32;

    const int s0 = 2 * q, s1 = 2 * q + 1;
    const int arow0 = s0 * 16 + (lane & 7) + ((lane >> 3) & 1) * 8;
    const int arow1 = s1 * 16 + (lane & 7) + ((lane >> 3) & 1) * 8;
    const uint32_t a_kb0 = ((lane >> 4) & 1) * 16;
    const uint32_t a_off0 = (uint32_t)arow0 * 128;
    const uint32_t a_off1 = (uint32_t)arow1 * 128;
    const uint32_t a_xr0  = (uint32_t)(arow0 & 7) << 4;
    const uint32_t a_xr1  = (uint32_t)(arow1 & 7) << 4;
    const int browl = (lane & 7) + ((lane >> 4) & 1) * 8;
    const uint32_t b_rb  = (uint32_t)browl * 128 + (uint32_t)grp * 4096;
    const uint32_t b_xr  = (uint32_t)(lane & 7) << 4;
    const uint32_t b_kb0 = ((lane >> 3) & 1) * 16;

    float d[2][4][4];
#pragma unroll
    for (int s = 0; s < 2; s++)
#pragma unroll
        for (int i = 0; i < 4; i++)
#pragma unroll
            for (int j = 0; j < 4; j++) d[s][i][j] = 0.0f;

    float4 wr[8];
    const float4 z4 = make_float4(0.f, 0.f, 0.f, 0.f);

#define LOAD_W(TL) do {                                                      \
    const int kp_ = kbase + (TL) * KTILE + kq * 4;                           \
    const bool ok_ = (kp_ < NRED);                                           \
    const float* wp_ = W + (size_t)(m0 + wrp * 2 + row_off) * NRED + kp_;    \
    _Pragma("unroll")                                                        \
    for (int i = 0; i < 8; i++)                                              \
        wr[i] = ok_ ? *(const float4*)(wp_ + (size_t)16 * i * NRED) : z4;    \
} while (0)

#define ASYNC_B(TL, BUF) do {                                                \
    const __nv_bfloat16* src_ = g_B + (size_t)brow * KPAD                    \
                              + (kbase + (TL) * KTILE) + (bcol >> 1);        \
    const uint32_t db_ = sb + SM_B + (BUF) * SM_BSTG;                        \
    const uint32_t bo_ = (uint32_t)brow * 128 + bcol;                        \
    cpasync16(db_ + sw128(bo_),      src_);                                  \
    cpasync16(db_ + sw128(bo_ + 16), src_ + 8);                              \
    cpasync_commit();                                                        \
} while (0)

#define STS_A(BUF) do {                                                      \
    char* ab_ = smem + SM_A + (BUF) * SM_ASTG;                               \
    _Pragma("unroll")                                                        \
    for (int i = 0; i < 8; i++) {                                            \
        const int row_ = i * 16 + wrp * 2 + row_off;                         \
        const uint32_t sw_ = sw128((uint32_t)row_ * 128 + kq * 8);           \
        float4 f_ = wr[i];                                                   \
        __nv_bfloat16 h0,h1,h2,h3,l0,l1,l2,l3;                               \
        split2(f_.x, h0, l0); split2(f_.y, h1, l1);                          \
        split2(f_.z, h2, l2); split2(f_.w, h3, l3);                          \
        *(uint2*)(ab_ + sw_)         = make_uint2(packbf(h0,h1), packbf(h2,h3)); \
        *(uint2*)(ab_ + sw_ + 16384) = make_uint2(packbf(l0,l1), packbf(l2,l3)); \
    }                                                                        \
} while (0)

#define COMPUTE(BUF) do {                                                    \
    const uint32_t sa_ = sb + SM_A + (BUF) * SM_ASTG;                        \
    const uint32_t sB_ = sb + SM_B + (BUF) * SM_BSTG;                        \
    _Pragma("unroll")                                                        \
    for (int ks = 0; ks < 4; ks++) {                                         \
        uint32_t ah0[4], ah1[4], bf[2][4];                                   \
        const uint32_t kb_ = (uint32_t)(ks * 32) + a_kb0;                    \
        LDSM4(ah0, sa_ + a_off0 + (kb_ ^ a_xr0));                            \
        LDSM4(ah1, sa_ + a_off1 + (kb_ ^ a_xr1));                            \
        const uint32_t bkb_ = ((uint32_t)(ks * 32) + b_kb0) ^ b_xr;          \
        LDSM4(bf[0], sB_ + b_rb + bkb_);                                     \
        LDSM4(bf[1], sB_ + 2048 + b_rb + bkb_);                              \
        MMA16816(d[0][0], ah0, bf[0][0], bf[0][1]);                          \
        MMA16816(d[0][1], ah0, bf[0][2], bf[0][3]);                          \
        MMA16816(d[0][2], ah0, bf[1][0], bf[1][1]);                          \
        MMA16816(d[0][3], ah0, bf[1][2], bf[1][3]);                          \
        MMA16816(d[1][0], ah1, bf[0][0], bf[0][1]);                          \
        MMA16816(d[1][1], ah1, bf[0][2], bf[0][3]);                          \
        MMA16816(d[1][2], ah1, bf[1][0], bf[1][1]);                          \
        MMA16816(d[1][3], ah1, bf[1][2], bf[1][3]);                          \
        if (grp == 0) {                                                      \
            uint32_t al0[4], al1[4];                                         \
            LDSM4(al0, sa_ + 16384 + a_off0 + (kb_ ^ a_xr0));                \
            LDSM4(al1, sa_ + 16384 + a_off1 + (kb_ ^ a_xr1));                \
            MMA16816(d[0][0], al0, bf[0][0], bf[0][1]);                      \
            MMA16816(d[0][1], al0, bf[0][2], bf[0][3]);                      \
            MMA16816(d[0][2], al0, bf[1][0], bf[1][1]);                      \
            MMA16816(d[0][3], al0, bf[1][2], bf[1][3]);                      \
            MMA16816(d[1][0], al1, bf[0][0], bf[0][1]);                      \
            MMA16816(d[1][1], al1, bf[0][2], bf[0][3]);                      \
            MMA16816(d[1][2], al1, bf[1][0], bf[1][1]);                      \
            MMA16816(d[1][3], al1, bf[1][2], bf[1][3]);                      \
        }                                                                    \
    }                                                                        \
} while (0)

    ASYNC_B(0, 0);
    LOAD_W(0);
    STS_A(0);
    cpasync_wait0();
    __syncthreads();

    for (int tl = 0; tl < NT; tl++) {
        if (tl + 1 < NT) {
            ASYNC_B(tl + 1, (tl + 1) & 1);
            LOAD_W(tl + 1);
        }
        COMPUTE(tl & 1);
        if (tl + 1 < NT) {
            STS_A((tl + 1) & 1);
            cpasync_wait0();
            __syncthreads();
        }
    }

    __syncthreads();
    float* es = (float*)smem;
    const int eidx = (q * 32 + lane) * 33;
    if (grp == 1) {
#pragma unroll
        for (int s = 0; s < 2; s++)
#pragma unroll
            for (int i = 0; i < 4; i++)
#pragma unroll
                for (int j = 0; j < 4; j++)
                    es[eidx + s * 16 + i * 4 + j] = d[s][i][j];
    }
    __syncthreads();
    if (grp == 0) {
        float* gp = g_partial + (size_t)split * (TT * KFEAT) + m0;
        const int rbase = lane >> 2;
        const int c0 = (lane & 3) * 2;
#pragma unroll
        for (int s = 0; s < 2; s++) {
            const int feat = (2 * q + s) * 16 + rbase;
#pragma unroll
            for (int nt = 0; nt < 4; nt++) {
                const int t0 = nt * 8 + c0;
                float v0 = d[s][nt][0] + es[eidx + s * 16 + nt * 4 + 0];
                float v1 = d[s][nt][1] + es[eidx + s * 16 + nt * 4 + 1];
                float v2 = d[s][nt][2] + es[eidx + s * 16 + nt * 4 + 2];
                float v3 = d[s][nt][3] + es[eidx + s * 16 + nt * 4 + 3];
                gp[(size_t)t0 * KFEAT + feat]           = v0;
                gp[(size_t)(t0 + 1) * KFEAT + feat]     = v1;
                gp[(size_t)t0 * KFEAT + feat + 8]       = v2;
                gp[(size_t)(t0 + 1) * KFEAT + feat + 8] = v3;
            }
        }
    }
}

// ---------------------------------------------------------------------------
// Fused reduce + selection. 32 blocks x 512 threads.
// ---------------------------------------------------------------------------
__global__ void __launch_bounds__(512, 1)
reduce_sel_kernel(float* __restrict__ out) {
    const int k = threadIdx.x;
    {
        const int j = blockIdx.x * 512 + k;
        float s = 0.0f;
#pragma unroll 8
        for (int sp = 0; sp < SPLITS; sp++) s += g_partial[sp * (TT * KFEAT) + j];
        g_dot[j] = s;
    }

    __shared__ int is_last;
    __threadfence();
    __syncthreads();
    if (k == 0) is_last = (atomicAdd(&g_arrive, 1) == RS_BLOCKS - 1);
    __syncthreads();
    if (!is_last) return;
    __threadfence();

    __shared__ ull   key_s[KFEAT];
    __shared__ int   win_s[KFEAT];
    __shared__ float red_s[16];
    __shared__ float v_s;

    float pot[TT];
    int nspk = 0;
#pragma unroll
    for (int t = 0; t < TT; t++) {
        float dd = g_dot[t * KFEAT + k];
        pot[t] = dd;
        nspk += (dd > THRESH) ? 1 : 0;
    }
    int first = TT - nspk;
    if (first > TT - 1) first = TT - 1;
    if (first < 0) first = 0;
    float dv = g_dot[first * KFEAT + k];
    float value = (dv > THRESH) ? dv : 0.0f;
    float sval = (nspk > 0) ? value : 0.0f;

    float m = sval;
#pragma unroll
    for (int o = 16; o > 0; o >>= 1)
        m = fmaxf(m, __shfl_xor_sync(0xffffffffu, m, o));
    if ((k & 31) == 0) red_s[k >> 5] = m;
    win_s[k] = 0;
    __syncthreads();
    if (k == 0) {
        float mm = red_s[0];
#pragma unroll
        for (int i = 1; i < 16; i++) mm = fmaxf(mm, red_s[i]);
        v_s = mm * (float)TT;
    }
    __syncthreads();

    const float fns = (float)nspk;
    const float total = fns * value + fns * v_s;   // >= 0 always
    ull key = ((ull)__float_as_uint(total) << 32)
            | (ull)(KFEAT - 1 - k);

#define INTRA_STAGE(KK, J) do {                                              \
    ull other_ = __shfl_xor_sync(0xffffffffu, key, (J));                     \
    const bool up_ = ((k & (KK)) == 0);                                      \
    const bool lo_ = ((k & (J)) == 0);                                       \
    const bool keepmin_ = (up_ == lo_);                                      \
    key = keepmin_ ? (key < other_ ? key : other_)                           \
                   : (key > other_ ? key : other_);                          \
} while (0)

#define CROSS_STAGE(KK, J) do {                                              \
    key_s[k] = key;                                                          \
    __syncthreads();                                                         \
    ull other_ = key_s[k ^ (J)];                                             \
    const bool up_ = ((k & (KK)) == 0);                                      \
    const bool lo_ = ((k & (J)) == 0);                                       \
    const bool keepmin_ = (up_ == lo_);                                      \
    key = keepmin_ ? (key < other_ ? key : other_)                           \
                   : (key > other_ ? key : other_);                          \
    __syncthreads();                                                         \
} while (0)

    INTRA_STAGE(2, 1);
    INTRA_STAGE(4, 2);  INTRA_STAGE(4, 1);
    INTRA_STAGE(8, 4);  INTRA_STAGE(8, 2);  INTRA_STAGE(8, 1);
    INTRA_STAGE(16, 8); INTRA_STAGE(16, 4); INTRA_STAGE(16, 2); INTRA_STAGE(16, 1);
    INTRA_STAGE(32, 16); INTRA_STAGE(32, 8); INTRA_STAGE(32, 4);
    INTRA_STAGE(32, 2);  INTRA_STAGE(32, 1);
    CROSS_STAGE(64, 32);
    INTRA_STAGE(64, 16); INTRA_STAGE(64, 8); INTRA_STAGE(64, 4);
    INTRA_STAGE(64, 2);  INTRA_STAGE(64, 1);
    CROSS_STAGE(128, 64); CROSS_STAGE(128, 32);
    INTRA_STAGE(128, 16); INTRA_STAGE(128, 8); INTRA_STAGE(128, 4);
    INTRA_STAGE(128, 2);  INTRA_STAGE(128, 1);
    CROSS_STAGE(256, 128); CROSS_STAGE(256, 64); CROSS_STAGE(256, 32);
    INTRA_STAGE(256, 16); INTRA_STAGE(256, 8); INTRA_STAGE(256, 4);
    INTRA_STAGE(256, 2);  INTRA_STAGE(256, 1);
    CROSS_STAGE(512, 256); CROSS_STAGE(512, 128); CROSS_STAGE(512, 64);
    CROSS_STAGE(512, 32);
    INTRA_STAGE(512, 16); INTRA_STAGE(512, 8); INTRA_STAGE(512, 4);
    INTRA_STAGE(512, 2);  INTRA_STAGE(512, 1);

    if (k >= KFEAT - KWTA) {
        if ((uint32_t)(key >> 32) != 0u) {
            const int idx = KFEAT - 1 - (int)(key & 0x1ffull);
            win_s[idx] = 1;
        }
    }
    __syncthreads();

    const bool win = (win_s[k] != 0);
#pragma unroll
    for (int t = 0; t < TT; t++)
        out[t * KFEAT + k] = (win && pot[t] > THRESH) ? 1.0f : 0.0f;
}

// ---------------------------------------------------------------------------
extern "C" void kernel_launch(void* const* d_in, const int* in_sizes, int n_in,
                              void* d_out, int out_size) {
    const float* a = (const float*)d_in[0];
    const float* b = (const float*)d_in[1];
    const float* rec = a;
    const float* wgt = b;
    if (in_sizes[0] > in_sizes[1]) { rec = b; wgt = a; }

    cudaFuncSetAttribute(gemm_kernel,
                         cudaFuncAttributeMaxDynamicSharedMemorySize, SMEMB);

    dim3 cgrid((KPAD / 4 + 255) / 256, TT);
    conv_kernel<<<cgrid, 256>>>(rec);
    dim3 grid(SPLITS, 4);
    gemm_kernel<<<grid, 256, SMEMB>>>(wgt);
    reduce_sel_kernel<<<RS_BLOCKS, 512>>>((float*)d_out);
}

// round 14
// speedup vs baseline: 1.2340x; 1.0295x over previous
#include <cuda_runtime.h>
#include <cuda_bf16.h>
#include <cstdint>

// ---------------------------------------------------------------------------
// Problem constants
#define NRED   100000
#define TT     32
#define KFEAT  512
#define THRESH 10.0f
#define KWTA   16

// GEMM tiling: 74 k-splits x 4 m-tiles = 296 CTAs (2 CTAs/SM)  [R7 proven]
#define SPLITS 74
#define KTILE  64
#define NT     22
#define CHUNK  (KTILE * NT)        // 1408
#define MTILE  128

#define SM_A    0
#define SM_ASTG 32768
#define SM_B    (2 * SM_ASTG)      // 65536
#define SM_BSTG 8192
#define SMEMB   (SM_B + 2 * SM_BSTG)   // 81920

#define RS_BLOCKS 32               // reduce_sel grid

// Device scratch (static — no dynamic allocation allowed)
__device__ float g_partial[SPLITS * TT * KFEAT];
__device__ float g_dot[TT * KFEAT];                // [t][feat]
__device__ int   g_arrive;                         // last-block counter

typedef unsigned long long ull;

// ---------------------------------------------------------------------------
__device__ __forceinline__ uint32_t smem_u32(const void* p) {
    uint32_t a;
    asm("{ .reg .u64 t; cvta.to.shared.u64 t, %1; cvt.u32.u64 %0, t; }"
        : "=r"(a) : "l"(p));
    return a;
}
__device__ __forceinline__ uint32_t sw128(uint32_t off) {
    return off ^ ((off >> 3) & 0x70);
}
__device__ __forceinline__ uint32_t packbf(__nv_bfloat16 a, __nv_bfloat16 b) {
    __nv_bfloat162 v; v.x = a; v.y = b;
    return *reinterpret_cast<uint32_t*>(&v);
}
__device__ __forceinline__ void split2(float x, __nv_bfloat16& h, __nv_bfloat16& l) {
    h = __float2bfloat16(x);
    l = __float2bfloat16(x - __bfloat162float(h));
}
#define LDSM4(R, ADDR)                                                        \
    asm volatile("ldmatrix.sync.aligned.m8n8.x4.shared.b16 {%0,%1,%2,%3}, [%4];" \
                 : "=r"((R)[0]), "=r"((R)[1]), "=r"((R)[2]), "=r"((R)[3])     \
                 : "r"(ADDR))
#define MMA16816(D, A, B0, B1)                                                \
    asm volatile("mma.sync.aligned.m16n8k16.row.col.f32.bf16.bf16.f32 "       \
                 "{%0,%1,%2,%3}, {%4,%5,%6,%7}, {%8,%9}, {%0,%1,%2,%3};"      \
                 : "+f"((D)[0]), "+f"((D)[1]), "+f"((D)[2]), "+f"((D)[3])     \
                 : "r"((A)[0]), "r"((A)[1]), "r"((A)[2]), "r"((A)[3]),        \
                   "r"(B0), "r"(B1))

// ---------------------------------------------------------------------------
// GEMM: bf16 3-term split, R-split fused into the B loader (no conv pass).
// grid (74, 4), 256 threads, 2 CTAs/SM.
// ---------------------------------------------------------------------------
__global__ void __launch_bounds__(256, 2)
gemm_kernel(const float* __restrict__ W, const float* __restrict__ R) {
    extern __shared__ char smem[];
    const uint32_t sb = smem_u32(smem);

    const int tid  = threadIdx.x;
    const int lane = tid & 31;
    const int wrp  = tid >> 5;
    const int q    = wrp & 3;
    const int grp  = wrp >> 2;
    const int split = blockIdx.x;
    const int m0    = blockIdx.y * MTILE;
    const int kbase = split * CHUNK;

    if (split == 0 && blockIdx.y == 0 && tid == 0) g_arrive = 0;

    // W loader
    const int row_off = lane >> 4;
    const int kq      = lane & 15;
    // B loader (fused split): thread = (t, 8-float chunk)
    const int bt  = tid >> 3;                  // 0..31 (timestep)
    const int bkc = tid & 7;                   // 0..7  (8 floats each)
    const uint32_t bo = (uint32_t)bt * 128 + (uint32_t)bkc * 16;

    const int s0 = 2 * q, s1 = 2 * q + 1;
    const int arow0 = s0 * 16 + (lane & 7) + ((lane >> 3) & 1) * 8;
    const int arow1 = s1 * 16 + (lane & 7) + ((lane >> 3) & 1) * 8;
    const uint32_t a_kb0 = ((lane >> 4) & 1) * 16;
    const uint32_t a_off0 = (uint32_t)arow0 * 128;
    const uint32_t a_off1 = (uint32_t)arow1 * 128;
    const uint32_t a_xr0  = (uint32_t)(arow0 & 7) << 4;
    const uint32_t a_xr1  = (uint32_t)(arow1 & 7) << 4;
    const int browl = (lane & 7) + ((lane >> 4) & 1) * 8;
    const uint32_t b_rb  = (uint32_t)browl * 128 + (uint32_t)grp * 4096;
    const uint32_t b_xr  = (uint32_t)(lane & 7) << 4;
    const uint32_t b_kb0 = ((lane >> 3) & 1) * 16;

    float d[2][4][4];
#pragma unroll
    for (int s = 0; s < 2; s++)
#pragma unroll
        for (int i = 0; i < 4; i++)
#pragma unroll
            for (int j = 0; j < 4; j++) d[s][i][j] = 0.0f;

    float4 wr[8];
    float4 br0, br1;
    const float4 z4 = make_float4(0.f, 0.f, 0.f, 0.f);

#define LOAD_W(TL) do {                                                      \
    const int kp_ = kbase + (TL) * KTILE + kq * 4;                           \
    const bool ok_ = (kp_ < NRED);                                           \
    const float* wp_ = W + (size_t)(m0 + wrp * 2 + row_off) * NRED + kp_;    \
    _Pragma("unroll")                                                        \
    for (int i = 0; i < 8; i++)                                              \
        wr[i] = ok_ ? *(const float4*)(wp_ + (size_t)16 * i * NRED) : z4;    \
} while (0)

#define LOAD_B(TL) do {                                                      \
    const int kp_ = kbase + (TL) * KTILE + bkc * 8;                          \
    const bool ok_ = (kp_ < NRED);                                           \
    const float* rp_ = R + (size_t)bt * NRED + kp_;                          \
    br0 = ok_ ? *(const float4*)(rp_)     : z4;                              \
    br1 = ok_ ? *(const float4*)(rp_ + 4) : z4;                              \
} while (0)

#define STS_B(BUF) do {                                                      \
    char* bb_ = smem + SM_B + (BUF) * SM_BSTG;                               \
    __nv_bfloat16 h0,h1,h2,h3,h4,h5,h6,h7,l0,l1,l2,l3,l4,l5,l6,l7;           \
    split2(br0.x,h0,l0); split2(br0.y,h1,l1);                                \
    split2(br0.z,h2,l2); split2(br0.w,h3,l3);                                \
    split2(br1.x,h4,l4); split2(br1.y,h5,l5);                                \
    split2(br1.z,h6,l6); split2(br1.w,h7,l7);                                \
    *(uint4*)(bb_ + sw128(bo)) =                                             \
        make_uint4(packbf(h0,h1), packbf(h2,h3), packbf(h4,h5), packbf(h6,h7)); \
    *(uint4*)(bb_ + sw128(bo + 4096)) =                                      \
        make_uint4(packbf(l0,l1), packbf(l2,l3), packbf(l4,l5), packbf(l6,l7)); \
} while (0)

#define STS_A(BUF) do {                                                      \
    char* ab_ = smem + SM_A + (BUF) * SM_ASTG;                               \
    _Pragma("unroll")                                                        \
    for (int i = 0; i < 8; i++) {                                            \
        const int row_ = i * 16 + wrp * 2 + row_off;                         \
        const uint32_t sw_ = sw128((uint32_t)row_ * 128 + kq * 8);           \
        float4 f_ = wr[i];                                                   \
        __nv_bfloat16 h0,h1,h2,h3,l0,l1,l2,l3;                               \
        split2(f_.x, h0, l0); split2(f_.y, h1, l1);                          \
        split2(f_.z, h2, l2); split2(f_.w, h3, l3);                          \
        *(uint2*)(ab_ + sw_)         = make_uint2(packbf(h0,h1), packbf(h2,h3)); \
        *(uint2*)(ab_ + sw_ + 16384) = make_uint2(packbf(l0,l1), packbf(l2,l3)); \
    }                                                                        \
} while (0)

#define COMPUTE(BUF) do {                                                    \
    const uint32_t sa_ = sb + SM_A + (BUF) * SM_ASTG;                        \
    const uint32_t sB_ = sb + SM_B + (BUF) * SM_BSTG;                        \
    _Pragma("unroll")                                                        \
    for (int ks = 0; ks < 4; ks++) {                                         \
        uint32_t ah0[4], ah1[4], bf[2][4];                                   \
        const uint32_t kb_ = (uint32_t)(ks * 32) + a_kb0;                    \
        LDSM4(ah0, sa_ + a_off0 + (kb_ ^ a_xr0));                            \
        LDSM4(ah1, sa_ + a_off1 + (kb_ ^ a_xr1));                            \
        const uint32_t bkb_ = ((uint32_t)(ks * 32) + b_kb0) ^ b_xr;          \
        LDSM4(bf[0], sB_ + b_rb + bkb_);                                     \
        LDSM4(bf[1], sB_ + 2048 + b_rb + bkb_);                              \
        MMA16816(d[0][0], ah0, bf[0][0], bf[0][1]);                          \
        MMA16816(d[0][1], ah0, bf[0][2], bf[0][3]);                          \
        MMA16816(d[0][2], ah0, bf[1][0], bf[1][1]);                          \
        MMA16816(d[0][3], ah0, bf[1][2], bf[1][3]);                          \
        MMA16816(d[1][0], ah1, bf[0][0], bf[0][1]);                          \
        MMA16816(d[1][1], ah1, bf[0][2], bf[0][3]);                          \
        MMA16816(d[1][2], ah1, bf[1][0], bf[1][1]);                          \
        MMA16816(d[1][3], ah1, bf[1][2], bf[1][3]);                          \
        if (grp == 0) {                                                      \
            uint32_t al0[4], al1[4];                                         \
            LDSM4(al0, sa_ + 16384 + a_off0 + (kb_ ^ a_xr0));                \
            LDSM4(al1, sa_ + 16384 + a_off1 + (kb_ ^ a_xr1));                \
            MMA16816(d[0][0], al0, bf[0][0], bf[0][1]);                      \
            MMA16816(d[0][1], al0, bf[0][2], bf[0][3]);                      \
            MMA16816(d[0][2], al0, bf[1][0], bf[1][1]);                      \
            MMA16816(d[0][3], al0, bf[1][2], bf[1][3]);                      \
            MMA16816(d[1][0], al1, bf[0][0], bf[0][1]);                      \
            MMA16816(d[1][1], al1, bf[0][2], bf[0][3]);                      \
            MMA16816(d[1][2], al1, bf[1][0], bf[1][1]);                      \
            MMA16816(d[1][3], al1, bf[1][2], bf[1][3]);                      \
        }                                                                    \
    }                                                                        \
} while (0)

    LOAD_B(0);
    LOAD_W(0);
    STS_B(0);
    STS_A(0);
    __syncthreads();

    for (int tl = 0; tl < NT; tl++) {
        if (tl + 1 < NT) {
            LOAD_B(tl + 1);
            LOAD_W(tl + 1);
        }
        COMPUTE(tl & 1);
        if (tl + 1 < NT) {
            STS_B((tl + 1) & 1);
            STS_A((tl + 1) & 1);
            __syncthreads();
        }
    }

    __syncthreads();
    float* es = (float*)smem;
    const int eidx = (q * 32 + lane) * 33;
    if (grp == 1) {
#pragma unroll
        for (int s = 0; s < 2; s++)
#pragma unroll
            for (int i = 0; i < 4; i++)
#pragma unroll
                for (int j = 0; j < 4; j++)
                    es[eidx + s * 16 + i * 4 + j] = d[s][i][j];
    }
    __syncthreads();
    if (grp == 0) {
        float* gp = g_partial + (size_t)split * (TT * KFEAT) + m0;
        const int rbase = lane >> 2;
        const int c0 = (lane & 3) * 2;
#pragma unroll
        for (int s = 0; s < 2; s++) {
            const int feat = (2 * q + s) * 16 + rbase;
#pragma unroll
            for (int nt = 0; nt < 4; nt++) {
                const int t0 = nt * 8 + c0;
                float v0 = d[s][nt][0] + es[eidx + s * 16 + nt * 4 + 0];
                float v1 = d[s][nt][1] + es[eidx + s * 16 + nt * 4 + 1];
                float v2 = d[s][nt][2] + es[eidx + s * 16 + nt * 4 + 2];
                float v3 = d[s][nt][3] + es[eidx + s * 16 + nt * 4 + 3];
                gp[(size_t)t0 * KFEAT + feat]           = v0;
                gp[(size_t)(t0 + 1) * KFEAT + feat]     = v1;
                gp[(size_t)t0 * KFEAT + feat + 8]       = v2;
                gp[(size_t)(t0 + 1) * KFEAT + feat + 8] = v3;
            }
        }
    }
}

// ---------------------------------------------------------------------------
// Fused reduce + selection. 32 blocks x 512 threads.
// ---------------------------------------------------------------------------
__global__ void __launch_bounds__(512, 1)
reduce_sel_kernel(float* __restrict__ out) {
    const int k = threadIdx.x;
    {
        const int j = blockIdx.x * 512 + k;
        float s = 0.0f;
#pragma unroll 8
        for (int sp = 0; sp < SPLITS; sp++) s += g_partial[sp * (TT * KFEAT) + j];
        g_dot[j] = s;
    }

    __shared__ int is_last;
    __threadfence();
    __syncthreads();
    if (k == 0) is_last = (atomicAdd(&g_arrive, 1) == RS_BLOCKS - 1);
    __syncthreads();
    if (!is_last) return;
    __threadfence();

    __shared__ ull   key_s[KFEAT];
    __shared__ int   win_s[KFEAT];
    __shared__ float red_s[16];
    __shared__ float v_s;

    float pot[TT];
    int nspk = 0;
#pragma unroll
    for (int t = 0; t < TT; t++) {
        float dd = g_dot[t * KFEAT + k];
        pot[t] = dd;
        nspk += (dd > THRESH) ? 1 : 0;
    }
    int first = TT - nspk;
    if (first > TT - 1) first = TT - 1;
    if (first < 0) first = 0;
    float dv = g_dot[first * KFEAT + k];
    float value = (dv > THRESH) ? dv : 0.0f;
    float sval = (nspk > 0) ? value : 0.0f;

    float m = sval;
#pragma unroll
    for (int o = 16; o > 0; o >>= 1)
        m = fmaxf(m, __shfl_xor_sync(0xffffffffu, m, o));
    if ((k & 31) == 0) red_s[k >> 5] = m;
    win_s[k] = 0;
    __syncthreads();
    if (k == 0) {
        float mm = red_s[0];
#pragma unroll
        for (int i = 1; i < 16; i++) mm = fmaxf(mm, red_s[i]);
        v_s = mm * (float)TT;
    }
    __syncthreads();

    const float fns = (float)nspk;
    const float total = fns * value + fns * v_s;   // >= 0 always
    ull key = ((ull)__float_as_uint(total) << 32)
            | (ull)(KFEAT - 1 - k);

#define INTRA_STAGE(KK, J) do {                                              \
    ull other_ = __shfl_xor_sync(0xffffffffu, key, (J));                     \
    const bool up_ = ((k & (KK)) == 0);                                      \
    const bool lo_ = ((k & (J)) == 0);                                       \
    const bool keepmin_ = (up_ == lo_);                                      \
    key = keepmin_ ? (key < other_ ? key : other_)                           \
                   : (key > other_ ? key : other_);                          \
} while (0)

#define CROSS_STAGE(KK, J) do {                                              \
    key_s[k] = key;                                                          \
    __syncthreads();                                                         \
    ull other_ = key_s[k ^ (J)];                                             \
    const bool up_ = ((k & (KK)) == 0);                                      \
    const bool lo_ = ((k & (J)) == 0);                                       \
    const bool keepmin_ = (up_ == lo_);                                      \
    key = keepmin_ ? (key < other_ ? key : other_)                           \
                   : (key > other_ ? key : other_);                          \
    __syncthreads();                                                         \
} while (0)

    INTRA_STAGE(2, 1);
    INTRA_STAGE(4, 2);  INTRA_STAGE(4, 1);
    INTRA_STAGE(8, 4);  INTRA_STAGE(8, 2);  INTRA_STAGE(8, 1);
    INTRA_STAGE(16, 8); INTRA_STAGE(16, 4); INTRA_STAGE(16, 2); INTRA_STAGE(16, 1);
    INTRA_STAGE(32, 16); INTRA_STAGE(32, 8); INTRA_STAGE(32, 4);
    INTRA_STAGE(32, 2);  INTRA_STAGE(32, 1);
    CROSS_STAGE(64, 32);
    INTRA_STAGE(64, 16); INTRA_STAGE(64, 8); INTRA_STAGE(64, 4);
    INTRA_STAGE(64, 2);  INTRA_STAGE(64, 1);
    CROSS_STAGE(128, 64); CROSS_STAGE(128, 32);
    INTRA_STAGE(128, 16); INTRA_STAGE(128, 8); INTRA_STAGE(128, 4);
    INTRA_STAGE(128, 2);  INTRA_STAGE(128, 1);
    CROSS_STAGE(256, 128); CROSS_STAGE(256, 64); CROSS_STAGE(256, 32);
    INTRA_STAGE(256, 16); INTRA_STAGE(256, 8); INTRA_STAGE(256, 4);
    INTRA_STAGE(256, 2);  INTRA_STAGE(256, 1);
    CROSS_STAGE(512, 256); CROSS_STAGE(512, 128); CROSS_STAGE(512, 64);
    CROSS_STAGE(512, 32);
    INTRA_STAGE(512, 16); INTRA_STAGE(512, 8); INTRA_STAGE(512, 4);
    INTRA_STAGE(512, 2);  INTRA_STAGE(512, 1);

    if (k >= KFEAT - KWTA) {
        if ((uint32_t)(key >> 32) != 0u) {
            const int idx = KFEAT - 1 - (int)(key & 0x1ffull);
            win_s[idx] = 1;
        }
    }
    __syncthreads();

    const bool win = (win_s[k] != 0);
#pragma unroll
    for (int t = 0; t < TT; t++)
        out[t * KFEAT + k] = (win && pot[t] > THRESH) ? 1.0f : 0.0f;
}

// ---------------------------------------------------------------------------
extern "C" void kernel_launch(void* const* d_in, const int* in_sizes, int n_in,
                              void* d_out, int out_size) {
    const float* a = (const float*)d_in[0];
    const float* b = (const float*)d_in[1];
    const float* rec = a;
    const float* wgt = b;
    if (in_sizes[0] > in_sizes[1]) { rec = b; wgt = a; }

    cudaFuncSetAttribute(gemm_kernel,
                         cudaFuncAttributeMaxDynamicSharedMemorySize, SMEMB);

    dim3 grid(SPLITS, 4);
    gemm_kernel<<<grid, 256, SMEMB>>>(wgt, rec);
    reduce_sel_kernel<<<RS_BLOCKS, 512>>>((float*)d_out);
}

// round 15
// speedup vs baseline: 1.2735x; 1.0321x over previous
#include <cuda_runtime.h>
#include <cuda_bf16.h>
#include <cstdint>

// ---------------------------------------------------------------------------
// Problem constants
#define NRED   100000
#define TT     32
#define KFEAT  512
#define THRESH 10.0f
#define KWTA   16

// GEMM tiling: 74 k-splits x 4 m-tiles = 296 CTAs (2 CTAs/SM)  [R7 proven]
#define SPLITS 74
#define KTILE  64
#define NT     22
#define CHUNK  (KTILE * NT)        // 1408
#define MTILE  128

#define SM_A    0
#define SM_ASTG 32768
#define SM_B    (2 * SM_ASTG)      // 65536
#define SM_BSTG 8192
#define SMEMB   (SM_B + 2 * SM_BSTG)   // 81920

#define RS_BLOCKS 128              // reduce_sel grid

// Device scratch (static — no dynamic allocation allowed)
__device__ float g_partial[SPLITS * TT * KFEAT];
__device__ float g_dot[TT * KFEAT];                // [t][feat]
__device__ int   g_arrive;                         // last-block counter

typedef unsigned long long ull;

// ---------------------------------------------------------------------------
__device__ __forceinline__ uint32_t smem_u32(const void* p) {
    uint32_t a;
    asm("{ .reg .u64 t; cvta.to.shared.u64 t, %1; cvt.u32.u64 %0, t; }"
        : "=r"(a) : "l"(p));
    return a;
}
__device__ __forceinline__ uint32_t sw128(uint32_t off) {
    return off ^ ((off >> 3) & 0x70);
}
__device__ __forceinline__ uint32_t packbf(__nv_bfloat16 a, __nv_bfloat16 b) {
    __nv_bfloat162 v; v.x = a; v.y = b;
    return *reinterpret_cast<uint32_t*>(&v);
}
__device__ __forceinline__ void split2(float x, __nv_bfloat16& h, __nv_bfloat16& l) {
    h = __float2bfloat16(x);
    l = __float2bfloat16(x - __bfloat162float(h));
}
#define LDSM4(R, ADDR)                                                        \
    asm volatile("ldmatrix.sync.aligned.m8n8.x4.shared.b16 {%0,%1,%2,%3}, [%4];" \
                 : "=r"((R)[0]), "=r"((R)[1]), "=r"((R)[2]), "=r"((R)[3])     \
                 : "r"(ADDR))
#define MMA16816(D, A, B0, B1)                                                \
    asm volatile("mma.sync.aligned.m16n8k16.row.col.f32.bf16.bf16.f32 "       \
                 "{%0,%1,%2,%3}, {%4,%5,%6,%7}, {%8,%9}, {%0,%1,%2,%3};"      \
                 : "+f"((D)[0]), "+f"((D)[1]), "+f"((D)[2]), "+f"((D)[3])     \
                 : "r"((A)[0]), "r"((A)[1]), "r"((A)[2]), "r"((A)[3]),        \
                   "r"(B0), "r"(B1))

// ---------------------------------------------------------------------------
// GEMM: bf16 3-term split, R-split fused into the B loader (no conv pass).
// grid (74, 4), 256 threads, 2 CTAs/SM.  [R14 structure, unchanged]
// ---------------------------------------------------------------------------
__global__ void __launch_bounds__(256, 2)
gemm_kernel(const float* __restrict__ W, const float* __restrict__ R) {
    extern __shared__ char smem[];
    const uint32_t sb = smem_u32(smem);

    const int tid  = threadIdx.x;
    const int lane = tid & 31;
    const int wrp  = tid >> 5;
    const int q    = wrp & 3;
    const int grp  = wrp >> 2;
    const int split = blockIdx.x;
    const int m0    = blockIdx.y * MTILE;
    const int kbase = split * CHUNK;

    if (split == 0 && blockIdx.y == 0 && tid == 0) g_arrive = 0;

    const int row_off = lane >> 4;
    const int kq      = lane & 15;
    const int bt  = tid >> 3;
    const int bkc = tid & 7;
    const uint32_t bo = (uint32_t)bt * 128 + (uint32_t)bkc * 16;

    const int s0 = 2 * q, s1 = 2 * q + 1;
    const int arow0 = s0 * 16 + (lane & 7) + ((lane >> 3) & 1) * 8;
    const int arow1 = s1 * 16 + (lane & 7) + ((lane >> 3) & 1) * 8;
    const uint32_t a_kb0 = ((lane >> 4) & 1) * 16;
    const uint32_t a_off0 = (uint32_t)arow0 * 128;
    const uint32_t a_off1 = (uint32_t)arow1 * 128;
    const uint32_t a_xr0  = (uint32_t)(arow0 & 7) << 4;
    const uint32_t a_xr1  = (uint32_t)(arow1 & 7) << 4;
    const int browl = (lane & 7) + ((lane >> 4) & 1) * 8;
    const uint32_t b_rb  = (uint32_t)browl * 128 + (uint32_t)grp * 4096;
    const uint32_t b_xr  = (uint32_t)(lane & 7) << 4;
    const uint32_t b_kb0 = ((lane >> 3) & 1) * 16;

    float d[2][4][4];
#pragma unroll
    for (int s = 0; s < 2; s++)
#pragma unroll
        for (int i = 0; i < 4; i++)
#pragma unroll
            for (int j = 0; j < 4; j++) d[s][i][j] = 0.0f;

    float4 wr[8];
    float4 br0, br1;
    const float4 z4 = make_float4(0.f, 0.f, 0.f, 0.f);

#define LOAD_W(TL) do {                                                      \
    const int kp_ = kbase + (TL) * KTILE + kq * 4;                           \
    const bool ok_ = (kp_ < NRED);                                           \
    const float* wp_ = W + (size_t)(m0 + wrp * 2 + row_off) * NRED + kp_;    \
    _Pragma("unroll")                                                        \
    for (int i = 0; i < 8; i++)                                              \
        wr[i] = ok_ ? *(const float4*)(wp_ + (size_t)16 * i * NRED) : z4;    \
} while (0)

#define LOAD_B(TL) do {                                                      \
    const int kp_ = kbase + (TL) * KTILE + bkc * 8;                          \
    const bool ok_ = (kp_ < NRED);                                           \
    const float* rp_ = R + (size_t)bt * NRED + kp_;                          \
    br0 = ok_ ? *(const float4*)(rp_)     : z4;                              \
    br1 = ok_ ? *(const float4*)(rp_ + 4) : z4;                              \
} while (0)

#define STS_B(BUF) do {                                                      \
    char* bb_ = smem + SM_B + (BUF) * SM_BSTG;                               \
    __nv_bfloat16 h0,h1,h2,h3,h4,h5,h6,h7,l0,l1,l2,l3,l4,l5,l6,l7;           \
    split2(br0.x,h0,l0); split2(br0.y,h1,l1);                                \
    split2(br0.z,h2,l2); split2(br0.w,h3,l3);                                \
    split2(br1.x,h4,l4); split2(br1.y,h5,l5);                                \
    split2(br1.z,h6,l6); split2(br1.w,h7,l7);                                \
    *(uint4*)(bb_ + sw128(bo)) =                                             \
        make_uint4(packbf(h0,h1), packbf(h2,h3), packbf(h4,h5), packbf(h6,h7)); \
    *(uint4*)(bb_ + sw128(bo + 4096)) =                                      \
        make_uint4(packbf(l0,l1), packbf(l2,l3), packbf(l4,l5), packbf(l6,l7)); \
} while (0)

#define STS_A(BUF) do {                                                      \
    char* ab_ = smem + SM_A + (BUF) * SM_ASTG;                               \
    _Pragma("unroll")                                                        \
    for (int i = 0; i < 8; i++) {                                            \
        const int row_ = i * 16 + wrp * 2 + row_off;                         \
        const uint32_t sw_ = sw128((uint32_t)row_ * 128 + kq * 8);           \
        float4 f_ = wr[i];                                                   \
        __nv_bfloat16 h0,h1,h2,h3,l0,l1,l2,l3;                               \
        split2(f_.x, h0, l0); split2(f_.y, h1, l1);                          \
        split2(f_.z, h2, l2); split2(f_.w, h3, l3);                          \
        *(uint2*)(ab_ + sw_)         = make_uint2(packbf(h0,h1), packbf(h2,h3)); \
        *(uint2*)(ab_ + sw_ + 16384) = make_uint2(packbf(l0,l1), packbf(l2,l3)); \
    }                                                                        \
} while (0)

#define COMPUTE(BUF) do {                                                    \
    const uint32_t sa_ = sb + SM_A + (BUF) * SM_ASTG;                        \
    const uint32_t sB_ = sb + SM_B + (BUF) * SM_BSTG;                        \
    _Pragma("unroll")                                                        \
    for (int ks = 0; ks < 4; ks++) {                                         \
        uint32_t ah0[4], ah1[4], bf[2][4];                                   \
        const uint32_t kb_ = (uint32_t)(ks * 32) + a_kb0;                    \
        LDSM4(ah0, sa_ + a_off0 + (kb_ ^ a_xr0));                            \
        LDSM4(ah1, sa_ + a_off1 + (kb_ ^ a_xr1));                            \
        const uint32_t bkb_ = ((uint32_t)(ks * 32) + b_kb0) ^ b_xr;          \
        LDSM4(bf[0], sB_ + b_rb + bkb_);                                     \
        LDSM4(bf[1], sB_ + 2048 + b_rb + bkb_);                              \
        MMA16816(d[0][0], ah0, bf[0][0], bf[0][1]);                          \
        MMA16816(d[0][1], ah0, bf[0][2], bf[0][3]);                          \
        MMA16816(d[0][2], ah0, bf[1][0], bf[1][1]);                          \
        MMA16816(d[0][3], ah0, bf[1][2], bf[1][3]);                          \
        MMA16816(d[1][0], ah1, bf[0][0], bf[0][1]);                          \
        MMA16816(d[1][1], ah1, bf[0][2], bf[0][3]);                          \
        MMA16816(d[1][2], ah1, bf[1][0], bf[1][1]);                          \
        MMA16816(d[1][3], ah1, bf[1][2], bf[1][3]);                          \
        if (grp == 0) {                                                      \
            uint32_t al0[4], al1[4];                                         \
            LDSM4(al0, sa_ + 16384 + a_off0 + (kb_ ^ a_xr0));                \
            LDSM4(al1, sa_ + 16384 + a_off1 + (kb_ ^ a_xr1));                \
            MMA16816(d[0][0], al0, bf[0][0], bf[0][1]);                      \
            MMA16816(d[0][1], al0, bf[0][2], bf[0][3]);                      \
            MMA16816(d[0][2], al0, bf[1][0], bf[1][1]);                      \
            MMA16816(d[0][3], al0, bf[1][2], bf[1][3]);                      \
            MMA16816(d[1][0], al1, bf[0][0], bf[0][1]);                      \
            MMA16816(d[1][1], al1, bf[0][2], bf[0][3]);                      \
            MMA16816(d[1][2], al1, bf[1][0], bf[1][1]);                      \
            MMA16816(d[1][3], al1, bf[1][2], bf[1][3]);                      \
        }                                                                    \
    }                                                                        \
} while (0)

    LOAD_B(0);
    LOAD_W(0);
    STS_B(0);
    STS_A(0);
    __syncthreads();

    for (int tl = 0; tl < NT; tl++) {
        if (tl + 1 < NT) {
            LOAD_B(tl + 1);
            LOAD_W(tl + 1);
        }
        COMPUTE(tl & 1);
        if (tl + 1 < NT) {
            STS_B((tl + 1) & 1);
            STS_A((tl + 1) & 1);
            __syncthreads();
        }
    }

    __syncthreads();
    float* es = (float*)smem;
    const int eidx = (q * 32 + lane) * 33;
    if (grp == 1) {
#pragma unroll
        for (int s = 0; s < 2; s++)
#pragma unroll
            for (int i = 0; i < 4; i++)
#pragma unroll
                for (int j = 0; j < 4; j++)
                    es[eidx + s * 16 + i * 4 + j] = d[s][i][j];
    }
    __syncthreads();
    if (grp == 0) {
        float* gp = g_partial + (size_t)split * (TT * KFEAT) + m0;
        const int rbase = lane >> 2;
        const int c0 = (lane & 3) * 2;
#pragma unroll
        for (int s = 0; s < 2; s++) {
            const int feat = (2 * q + s) * 16 + rbase;
#pragma unroll
            for (int nt = 0; nt < 4; nt++) {
                const int t0 = nt * 8 + c0;
                float v0 = d[s][nt][0] + es[eidx + s * 16 + nt * 4 + 0];
                float v1 = d[s][nt][1] + es[eidx + s * 16 + nt * 4 + 1];
                float v2 = d[s][nt][2] + es[eidx + s * 16 + nt * 4 + 2];
                float v3 = d[s][nt][3] + es[eidx + s * 16 + nt * 4 + 3];
                gp[(size_t)t0 * KFEAT + feat]           = v0;
                gp[(size_t)(t0 + 1) * KFEAT + feat]     = v1;
                gp[(size_t)t0 * KFEAT + feat + 8]       = v2;
                gp[(size_t)(t0 + 1) * KFEAT + feat + 8] = v3;
            }
        }
    }
}

// ---------------------------------------------------------------------------
// Fused reduce + selection. 128 blocks x 512 threads.
// Block b owns j in [128b, 128b+128). Threads: j = tid&127 (coalesced),
// p = tid>>7 selects a quarter of the splits. Partials folded via smem in
// fixed order -> deterministic. Last-arriving block runs selection.
// ---------------------------------------------------------------------------
__global__ void __launch_bounds__(512, 1)
reduce_sel_kernel(float* __restrict__ out) {
    __shared__ float part_s[4][136];
    const int k = threadIdx.x;
    {
        const int jl = k & 127;
        const int p  = k >> 7;
        const int j  = blockIdx.x * 128 + jl;
        const int sp0 = (p * SPLITS) >> 2;
        const int sp1 = ((p + 1) * SPLITS) >> 2;
        float s = 0.0f;
#pragma unroll 4
        for (int sp = sp0; sp < sp1; sp++)
            s += g_partial[sp * (TT * KFEAT) + j];
        part_s[p][jl] = s;
        __syncthreads();
        if (k < 128) {
            float tot = ((part_s[0][k] + part_s[1][k])
                       + (part_s[2][k] + part_s[3][k]));
            g_dot[blockIdx.x * 128 + k] = tot;
        }
    }

    __shared__ int is_last;
    __threadfence();
    __syncthreads();
    if (k == 0) is_last = (atomicAdd(&g_arrive, 1) == RS_BLOCKS - 1);
    __syncthreads();
    if (!is_last) return;
    __threadfence();

    // ---- selection phase (this block only) ----
    __shared__ ull   key_s[KFEAT];
    __shared__ int   win_s[KFEAT];
    __shared__ float red_s[16];
    __shared__ float v_s;

    float pot[TT];
    int nspk = 0;
#pragma unroll
    for (int t = 0; t < TT; t++) {
        float dd = g_dot[t * KFEAT + k];
        pot[t] = dd;
        nspk += (dd > THRESH) ? 1 : 0;
    }
    int first = TT - nspk;
    if (first > TT - 1) first = TT - 1;
    if (first < 0) first = 0;
    float dv = g_dot[first * KFEAT + k];
    float value = (dv > THRESH) ? dv : 0.0f;
    float sval = (nspk > 0) ? value : 0.0f;

    float m = sval;
#pragma unroll
    for (int o = 16; o > 0; o >>= 1)
        m = fmaxf(m, __shfl_xor_sync(0xffffffffu, m, o));
    if ((k & 31) == 0) red_s[k >> 5] = m;
    win_s[k] = 0;
    __syncthreads();
    if (k == 0) {
        float mm = red_s[0];
#pragma unroll
        for (int i = 1; i < 16; i++) mm = fmaxf(mm, red_s[i]);
        v_s = mm * (float)TT;
    }
    __syncthreads();

    const float fns = (float)nspk;
    const float total = fns * value + fns * v_s;   // >= 0 always
    ull key = ((ull)__float_as_uint(total) << 32)
            | (ull)(KFEAT - 1 - k);

#define INTRA_STAGE(KK, J) do {                                              \
    ull other_ = __shfl_xor_sync(0xffffffffu, key, (J));                     \
    const bool up_ = ((k & (KK)) == 0);                                      \
    const bool lo_ = ((k & (J)) == 0);                                       \
    const bool keepmin_ = (up_ == lo_);                                      \
    key = keepmin_ ? (key < other_ ? key : other_)                           \
                   : (key > other_ ? key : other_);                          \
} while (0)

#define CROSS_STAGE(KK, J) do {                                              \
    key_s[k] = key;                                                          \
    __syncthreads();                                                         \
    ull other_ = key_s[k ^ (J)];                                             \
    const bool up_ = ((k & (KK)) == 0);                                      \
    const bool lo_ = ((k & (J)) == 0);                                       \
    const bool keepmin_ = (up_ == lo_);                                      \
    key = keepmin_ ? (key < other_ ? key : other_)                           \
                   : (key > other_ ? key : other_);                          \
    __syncthreads();                                                         \
} while (0)

    INTRA_STAGE(2, 1);
    INTRA_STAGE(4, 2);  INTRA_STAGE(4, 1);
    INTRA_STAGE(8, 4);  INTRA_STAGE(8, 2);  INTRA_STAGE(8, 1);
    INTRA_STAGE(16, 8); INTRA_STAGE(16, 4); INTRA_STAGE(16, 2); INTRA_STAGE(16, 1);
    INTRA_STAGE(32, 16); INTRA_STAGE(32, 8); INTRA_STAGE(32, 4);
    INTRA_STAGE(32, 2);  INTRA_STAGE(32, 1);
    CROSS_STAGE(64, 32);
    INTRA_STAGE(64, 16); INTRA_STAGE(64, 8); INTRA_STAGE(64, 4);
    INTRA_STAGE(64, 2);  INTRA_STAGE(64, 1);
    CROSS_STAGE(128, 64); CROSS_STAGE(128, 32);
    INTRA_STAGE(128, 16); INTRA_STAGE(128, 8); INTRA_STAGE(128, 4);
    INTRA_STAGE(128, 2);  INTRA_STAGE(128, 1);
    CROSS_STAGE(256, 128); CROSS_STAGE(256, 64); CROSS_STAGE(256, 32);
    INTRA_STAGE(256, 16); INTRA_STAGE(256, 8); INTRA_STAGE(256, 4);
    INTRA_STAGE(256, 2);  INTRA_STAGE(256, 1);
    CROSS_STAGE(512, 256); CROSS_STAGE(512, 128); CROSS_STAGE(512, 64);
    CROSS_STAGE(512, 32);
    INTRA_STAGE(512, 16); INTRA_STAGE(512, 8); INTRA_STAGE(512, 4);
    INTRA_STAGE(512, 2);  INTRA_STAGE(512, 1);

    if (k >= KFEAT - KWTA) {
        if ((uint32_t)(key >> 32) != 0u) {
            const int idx = KFEAT - 1 - (int)(key & 0x1ffull);
            win_s[idx] = 1;
        }
    }
    __syncthreads();

    const bool win = (win_s[k] != 0);
#pragma unroll
    for (int t = 0; t < TT; t++)
        out[t * KFEAT + k] = (win && pot[t] > THRESH) ? 1.0f : 0.0f;
}

// ---------------------------------------------------------------------------
extern "C" void kernel_launch(void* const* d_in, const int* in_sizes, int n_in,
                              void* d_out, int out_size) {
    const float* a = (const float*)d_in[0];
    const float* b = (const float*)d_in[1];
    const float* rec = a;
    const float* wgt = b;
    if (in_sizes[0] > in_sizes[1]) { rec = b; wgt = a; }

    cudaFuncSetAttribute(gemm_kernel,
                         cudaFuncAttributeMaxDynamicSharedMemorySize, SMEMB);

    dim3 grid(SPLITS, 4);
    gemm_kernel<<<grid, 256, SMEMB>>>(wgt, rec);
    reduce_sel_kernel<<<RS_BLOCKS, 512>>>((float*)d_out);
}